// round 7
// baseline (speedup 1.0000x reference)
#include <cuda_runtime.h>

#define NF 128
#define N_NODES 100000
#define E_MAX 2000000
#define PREP_NBLK 148
#define PREP_THR 256
#define SEG 676                      // ceil(100000/148)

// Scratch: static device globals (no runtime allocation allowed).
__device__ float4 g_agg4[(size_t)N_NODES * NF / 4];   // 51.2 MB mean-aggregated rows
__device__ float4 g_h4[(size_t)N_NODES * NF / 4];     // 51.2 MB hidden activations
__device__ int g_deg[N_NODES];                        // in-degree
__device__ int g_off[N_NODES];                        // CSR offsets
__device__ int g_cur[N_NODES];                        // fill cursors
__device__ int g_srcs[E_MAX];                         // src ids sorted by dst
__device__ int g_bsum[PREP_NBLK];                     // per-block scan sums
__device__ int g_bars[8];                             // software grid barriers
__device__ int g_is64;                                // edge_index dtype flag

// ---------------------------------------------------------------------------
// init: zero degrees + barrier slots, detect edge dtype (int64 ids < 2^31
// -> all high words zero; impossible for 64 random int32 indices).
// ---------------------------------------------------------------------------
__global__ void init_kernel(const int* __restrict__ ei_words) {
    int i = blockIdx.x * blockDim.x + threadIdx.x;
    if (i < N_NODES) g_deg[i] = 0;
    if (i < 8) g_bars[i] = 0;
    if (i == 0) {
        int is64 = 1;
        #pragma unroll
        for (int k = 0; k < 64; k++)
            if (ei_words[2 * k + 1] != 0) { is64 = 0; break; }
        g_is64 = is64;
    }
}

__device__ __forceinline__ int load_edge(const void* ei, long long idx) {
    return g_is64 ? (int)((const long long*)ei)[idx] : ((const int*)ei)[idx];
}

// Software grid barrier (slots pre-zeroed by init each launch -> replay-safe).
__device__ __forceinline__ void gbar(int slot) {
    __syncthreads();
    if (threadIdx.x == 0) {
        __threadfence();
        atomicAdd(&g_bars[slot], 1);
        while (atomicAdd(&g_bars[slot], 0) < (int)gridDim.x) {}
        __threadfence();
    }
    __syncthreads();
}

// ---------------------------------------------------------------------------
// Persistent prep kernel (148 blocks, all resident): hist -> barrier ->
// per-block segment scan -> barrier -> redundant smem scan of block sums ->
// final offsets -> barrier -> fill dst-sorted src lists.
// ---------------------------------------------------------------------------
__global__ __launch_bounds__(PREP_THR, 1) void prep_kernel(
    const void* __restrict__ ei, int E)
{
    int tid = threadIdx.x, lane = tid & 31, wid = tid >> 5;
    int gstride = gridDim.x * blockDim.x;
    int gid = blockIdx.x * blockDim.x + tid;

    // Phase A: degree histogram
    for (int e = gid; e < E; e += gstride) {
        int d = load_edge(ei, (long long)E + e);
        d = min(max(d, 0), N_NODES - 1);
        atomicAdd(&g_deg[d], 1);
    }
    gbar(0);

    // Phase B: per-block segment exclusive scan (segment = SEG nodes)
    __shared__ int wsum[8];
    __shared__ int carry_s;
    __shared__ int bs[PREP_NBLK];
    int seg0 = blockIdx.x * SEG;
    int segend = min(seg0 + SEG, N_NODES);
    if (tid == 0) carry_s = 0;
    __syncthreads();
    for (int base = seg0; base < seg0 + SEG; base += PREP_THR) {
        int i = base + tid;
        int v = (i < segend) ? g_deg[i] : 0;
        int s = v;
        #pragma unroll
        for (int d = 1; d < 32; d <<= 1) {
            int t = __shfl_up_sync(0xFFFFFFFFu, s, d);
            if (lane >= d) s += t;
        }
        if (lane == 31) wsum[wid] = s;
        __syncthreads();
        if (wid == 0 && lane < 8) {
            int ws = wsum[lane];
            #pragma unroll
            for (int d = 1; d < 8; d <<= 1) {
                int t = __shfl_up_sync(0xFFu, ws, d);
                if (lane >= d) ws += t;
            }
            wsum[lane] = ws;
        }
        __syncthreads();
        int woff = (wid == 0) ? 0 : wsum[wid - 1];
        if (i < segend) g_off[i] = carry_s + woff + s - v;   // block-local
        __syncthreads();
        if (tid == 0) carry_s += wsum[7];
        __syncthreads();
    }
    if (tid == 0) g_bsum[blockIdx.x] = carry_s;
    gbar(1);

    // Phase C: every block redundantly exclusive-scans the 148 block sums.
    if (tid < PREP_NBLK) bs[tid] = g_bsum[tid];
    __syncthreads();
    __shared__ int myoff_s;
    if (tid == 0) {
        int run = 0;
        for (int k = 0; k < PREP_NBLK; k++) { int t = bs[k]; bs[k] = run; run += t; }
        myoff_s = bs[blockIdx.x];
    }
    __syncthreads();
    int myoff = myoff_s;

    // Phase D: finalize offsets + cursors for this segment.
    for (int i = seg0 + tid; i < segend; i += PREP_THR) {
        int o = g_off[i] + myoff;
        g_off[i] = o;
        g_cur[i] = o;
    }
    gbar(2);

    // Phase E: fill dst-sorted src lists.
    for (int e = gid; e < E; e += gstride) {
        int s = load_edge(ei, e);
        int d = load_edge(ei, (long long)E + e);
        s = min(max(s, 0), N_NODES - 1);
        d = min(max(d, 0), N_NODES - 1);
        int pos = atomicAdd(&g_cur[d], 1);
        if (pos >= 0 && pos < E_MAX) g_srcs[pos] = s;
    }
}

// ---------------------------------------------------------------------------
// Gather-aggregate: one warp per node, 4-row unrolled gather (MLP=4).
// Each row = one coalesced LDG.128 per lane (512B). Writes the MEAN once.
// ---------------------------------------------------------------------------
__global__ __launch_bounds__(512) void aggregate_kernel(
    const float* __restrict__ feat, int use_h)
{
    const float4* f = use_h ? g_h4 : reinterpret_cast<const float4*>(feat);
    int w = (blockIdx.x * blockDim.x + threadIdx.x) >> 5;
    int lane = threadIdx.x & 31;
    if (w >= N_NODES) return;
    int off = g_off[w], deg = g_deg[w];
    float4 a0 = make_float4(0.f, 0.f, 0.f, 0.f);
    float4 a1 = make_float4(0.f, 0.f, 0.f, 0.f);
    for (int j0 = 0; j0 < deg; j0 += 32) {
        int nj = min(32, deg - j0);
        int my = (lane < nj) ? g_srcs[off + j0 + lane] : 0;
        int t = 0;
        for (; t + 4 <= nj; t += 4) {
            int s0 = __shfl_sync(0xFFFFFFFFu, my, t);
            int s1 = __shfl_sync(0xFFFFFFFFu, my, t + 1);
            int s2 = __shfl_sync(0xFFFFFFFFu, my, t + 2);
            int s3 = __shfl_sync(0xFFFFFFFFu, my, t + 3);
            float4 v0 = f[(size_t)s0 * 32 + lane];
            float4 v1 = f[(size_t)s1 * 32 + lane];
            float4 v2 = f[(size_t)s2 * 32 + lane];
            float4 v3 = f[(size_t)s3 * 32 + lane];
            a0.x += v0.x; a0.y += v0.y; a0.z += v0.z; a0.w += v0.w;
            a1.x += v1.x; a1.y += v1.y; a1.z += v1.z; a1.w += v1.w;
            a0.x += v2.x; a0.y += v2.y; a0.z += v2.z; a0.w += v2.w;
            a1.x += v3.x; a1.y += v3.y; a1.z += v3.z; a1.w += v3.w;
        }
        for (; t < nj; t++) {
            int s0 = __shfl_sync(0xFFFFFFFFu, my, t);
            float4 v0 = f[(size_t)s0 * 32 + lane];
            a0.x += v0.x; a0.y += v0.y; a0.z += v0.z; a0.w += v0.w;
        }
    }
    float iv = (deg > 0) ? 1.0f / (float)deg : 0.0f;
    float4 r;
    r.x = (a0.x + a1.x) * iv; r.y = (a0.y + a1.y) * iv;
    r.z = (a0.z + a1.z) * iv; r.w = (a0.w + a1.w) * iv;
    g_agg4[(size_t)w * 32 + lane] = r;
}

// Packed fp32x2 FMA (Blackwell): 2x the throughput of 3-reg FFMA.
#define FMA2(d, a, b) asm("fma.rn.f32x2 %0, %1, %2, %0;" : "+l"(d) : "l"(a), "l"(b))

// ---------------------------------------------------------------------------
// Fused SAGE linear with software-pipelined staging: the next 32-k chunk's
// agg/x values are prefetched into registers BEFORE computing the current
// chunk, hiding the ~250cyc L2 latency under 1024 FMA2s per chunk.
// 512 threads (16 warps, 4/SMSP), 8 rows/warp. Weights smem-transposed,
// stride 128; per-(row,k) inputs staged duplicated {a,a,x,x} -> one LDS.128
// broadcast (1 port cyc) feeds 4 FMA2.
// ---------------------------------------------------------------------------
template <bool RELU>
__global__ __launch_bounds__(512, 1) void gemm_kernel(
    const float* __restrict__ X,
    const float* __restrict__ Wl, const float* __restrict__ Wr,
    const float* __restrict__ bias, float* __restrict__ out, int N,
    int use_h_in, int use_h_out)
{
    const float* Xp = use_h_in ? reinterpret_cast<const float*>(g_h4) : X;
    float* op = use_h_out ? reinterpret_cast<float*>(g_h4) : out;
    const float* agg = reinterpret_cast<const float*>(g_agg4);

    extern __shared__ float smem[];
    float* s_wl = smem;                   // 128*128
    float* s_wr = smem + 128 * 128;       // 128*128
    float* s_b  = smem + 2 * 128 * 128;   // 128
    float* s_st = s_b + 128;              // 16 warps * 1024 floats

    int tid = threadIdx.x;
    for (int i = tid; i < 128 * 128; i += 512) {
        int n = i >> 7, k = i & 127;
        s_wl[k * 128 + n] = Wl[i];        // s_wl[k][n] = Wl[n][k]
        s_wr[k * 128 + n] = Wr[i];
    }
    if (tid < 128) s_b[tid] = bias[tid];
    __syncthreads();

    int warp = tid >> 5, lane = tid & 31;
    int lane4 = lane * 4;
    float* s_rw = s_st + warp * 1024;     // 8 rows * 128 floats

    unsigned long long b0 = *reinterpret_cast<const unsigned long long*>(s_b + lane4);
    unsigned long long b1 = *reinterpret_cast<const unsigned long long*>(s_b + lane4 + 2);

    for (int base = blockIdx.x * 128; base < N; base += gridDim.x * 128) {
        int row0 = base + warp * 8;
        unsigned long long acc[8][2];
        #pragma unroll
        for (int rr = 0; rr < 8; rr++) { acc[rr][0] = b0; acc[rr][1] = b1; }

        // prefetch chunk 0
        float pa[8], px[8];
        #pragma unroll
        for (int rr = 0; rr < 8; rr++) {
            int row = row0 + rr;
            if (row < N) {
                pa[rr] = agg[(size_t)row * NF + lane];
                px[rr] = Xp[(size_t)row * NF + lane];
            } else { pa[rr] = 0.f; px[rr] = 0.f; }
        }

        #pragma unroll
        for (int chunk = 0; chunk < 4; chunk++) {
            int kb = chunk * 32;
            __syncwarp();
            #pragma unroll
            for (int rr = 0; rr < 8; rr++)
                reinterpret_cast<float4*>(s_rw + rr * 128)[lane] =
                    make_float4(pa[rr], pa[rr], px[rr], px[rr]);
            __syncwarp();
            // prefetch next chunk while this chunk's FMAs run
            if (chunk < 3) {
                int kn = kb + 32;
                #pragma unroll
                for (int rr = 0; rr < 8; rr++) {
                    int row = row0 + rr;
                    if (row < N) {
                        pa[rr] = agg[(size_t)row * NF + kn + lane];
                        px[rr] = Xp[(size_t)row * NF + kn + lane];
                    }
                }
            }
            #pragma unroll 2
            for (int k = 0; k < 32; k++) {
                const float* wk = s_wl + (kb + k) * 128 + lane4;
                ulonglong2 WL = *reinterpret_cast<const ulonglong2*>(wk);
                ulonglong2 WR = *reinterpret_cast<const ulonglong2*>(wk + 128 * 128);
                #pragma unroll
                for (int rr = 0; rr < 8; rr++) {
                    ulonglong2 AX = *reinterpret_cast<const ulonglong2*>(
                        s_rw + rr * 128 + k * 4);   // {a,a | x,x} broadcast
                    FMA2(acc[rr][0], WL.x, AX.x);
                    FMA2(acc[rr][1], WL.y, AX.x);
                    FMA2(acc[rr][0], WR.x, AX.y);
                    FMA2(acc[rr][1], WR.y, AX.y);
                }
            }
        }
        #pragma unroll
        for (int rr = 0; rr < 8; rr++) {
            int row = row0 + rr;
            if (row < N) {
                float2 p0, p1;
                asm("mov.b64 {%0, %1}, %2;" : "=f"(p0.x), "=f"(p0.y) : "l"(acc[rr][0]));
                asm("mov.b64 {%0, %1}, %2;" : "=f"(p1.x), "=f"(p1.y) : "l"(acc[rr][1]));
                if (RELU) {
                    p0.x = fmaxf(p0.x, 0.f); p0.y = fmaxf(p0.y, 0.f);
                    p1.x = fmaxf(p1.x, 0.f); p1.y = fmaxf(p1.y, 0.f);
                }
                *reinterpret_cast<float4*>(op + (size_t)row * NF + lane4) =
                    make_float4(p0.x, p0.y, p1.x, p1.y);
            }
        }
    }
}

// ---------------------------------------------------------------------------
// init -> prep(hist+scan+fill, persistent) -> agg1 -> gemm1 -> agg2 -> gemm2
// Input identification by EXACT element count: 12.8M -> x; 16384 -> weights
// (w1_l, w1_r, w2_l, w2_r); 128 -> biases (b1, b2); else -> edge_index.
// ---------------------------------------------------------------------------
extern "C" void kernel_launch(void* const* d_in, const int* in_sizes, int n_in,
                              void* d_out, int out_size) {
    const float* x = nullptr;
    const void* ei = nullptr;
    const float* w[4] = {nullptr, nullptr, nullptr, nullptr};
    const float* b[2] = {nullptr, nullptr};
    int nw = 0, nb = 0, E = 0, N = N_NODES;

    for (int i = 0; i < n_in; i++) {
        int sz = in_sizes[i];
        if (sz == N_NODES * NF) {
            x = (const float*)d_in[i];
        } else if (sz == NF * NF) {
            if (nw < 4) w[nw++] = (const float*)d_in[i];
        } else if (sz == NF) {
            if (nb < 2) b[nb++] = (const float*)d_in[i];
        } else {
            ei = d_in[i];
            E = sz / 2;
        }
    }
    if (E > E_MAX) E = E_MAX;
    const float *w1l = w[0], *w1r = w[1], *w2l = w[2], *w2r = w[3];
    const float *b1 = b[0], *b2 = b[1];
    float* out = (float*)d_out;

    size_t smem_bytes = (size_t)(2 * 128 * 128 + 128 + 16 * 1024) * sizeof(float); // 197.1 KB
    cudaFuncSetAttribute(gemm_kernel<true>,  cudaFuncAttributeMaxDynamicSharedMemorySize, (int)smem_bytes);
    cudaFuncSetAttribute(gemm_kernel<false>, cudaFuncAttributeMaxDynamicSharedMemorySize, (int)smem_bytes);

    int agg_grid = (N_NODES * 32 + 511) / 512;   // one warp per node

    init_kernel<<<(N_NODES + 511) / 512, 512>>>((const int*)ei);
    prep_kernel<<<PREP_NBLK, PREP_THR>>>(ei, E);

    // Layer 1
    aggregate_kernel<<<agg_grid, 512>>>(x, 0);
    gemm_kernel<true><<<148, 512, smem_bytes>>>(x, w1l, w1r, b1, out, N, 0, 1);

    // Layer 2
    aggregate_kernel<<<agg_grid, 512>>>(x, 1);
    gemm_kernel<false><<<148, 512, smem_bytes>>>(x, w2l, w2r, b2, out, N, 1, 0);
}

// round 12
// speedup vs baseline: 1.4427x; 1.4427x over previous
#include <cuda_runtime.h>
#include <cuda_bf16.h>
#include <cstdint>

#define NF 128
#define N_NODES 100000
#define E_MAX 2000000
#define SCAN_BLK 1024
#define SCAN_NBLK ((N_NODES + SCAN_BLK - 1) / SCAN_BLK)   // 98

// Scratch: static device globals. Total ~112MB — same footprint as the last
// PASSING round (R6). (R9-R11 declared ~214MB of globals and tripped the
// harness alloc-guard with a constant 256MiB arena delta.)
__device__ float4 g_agg4[(size_t)N_NODES * NF / 4];   // 51.2 MB fp32 mean rows
__device__ float4 g_h4[(size_t)N_NODES * NF / 4];     // 51.2 MB fp32 hidden
__device__ int g_deg[N_NODES];
__device__ int g_off[N_NODES];
__device__ int g_cur[N_NODES];
__device__ int g_srcs[E_MAX];
__device__ int g_bsum[SCAN_NBLK];
__device__ int g_is64;

// ---------------------------------------------------------------------------
// helpers
// ---------------------------------------------------------------------------
__device__ __forceinline__ uint32_t smem_u32(const void* p) {
    uint32_t a;
    asm("{ .reg .u64 t; cvta.to.shared.u64 t, %1; cvt.u32.u64 %0, t; }"
        : "=r"(a) : "l"(p));
    return a;
}

__device__ __forceinline__ uint32_t pack2(__nv_bfloat16 a, __nv_bfloat16 b) {
    __nv_bfloat162 t = __halves2bfloat162(a, b);   // a = low half
    return *reinterpret_cast<uint32_t*>(&t);
}

__device__ __forceinline__ void bf_split(float v, __nv_bfloat16& h, __nv_bfloat16& l) {
    h = __float2bfloat16(v);
    l = __float2bfloat16(v - __bfloat162float(h));
}

// fp32 pair -> bf16 hi-pack + lo-pack
__device__ __forceinline__ void split_pack(float2 v, uint32_t& hp, uint32_t& lp) {
    __nv_bfloat16 h0, l0, h1, l1;
    bf_split(v.x, h0, l0);
    bf_split(v.y, h1, l1);
    hp = pack2(h0, h1);
    lp = pack2(l0, l1);
}

__device__ __forceinline__ void mma16816(float* d, const uint32_t* a,
                                         uint32_t b0, uint32_t b1) {
    asm volatile(
        "mma.sync.aligned.m16n8k16.row.col.f32.bf16.bf16.f32 "
        "{%0,%1,%2,%3}, {%4,%5,%6,%7}, {%8,%9}, {%0,%1,%2,%3};"
        : "+f"(d[0]), "+f"(d[1]), "+f"(d[2]), "+f"(d[3])
        : "r"(a[0]), "r"(a[1]), "r"(a[2]), "r"(a[3]), "r"(b0), "r"(b1));
}

__device__ __forceinline__ void ldsm_x4_trans(uint32_t* r, uint32_t addr) {
    asm volatile(
        "ldmatrix.sync.aligned.m8n8.x4.trans.shared.b16 {%0,%1,%2,%3}, [%4];"
        : "=r"(r[0]), "=r"(r[1]), "=r"(r[2]), "=r"(r[3]) : "r"(addr));
}

// ===========================================================================
// Preprocessing (identical to R6 — last fully-passing version)
// ===========================================================================
__global__ void init_kernel(const int* __restrict__ ei_words) {
    int i = blockIdx.x * blockDim.x + threadIdx.x;
    if (i < N_NODES) g_deg[i] = 0;
    if (i == 0) {
        int is64 = 1;
        #pragma unroll
        for (int k = 0; k < 64; k++)
            if (ei_words[2 * k + 1] != 0) { is64 = 0; break; }
        g_is64 = is64;
    }
}

__device__ __forceinline__ int load_edge(const void* ei, long long idx) {
    return g_is64 ? (int)((const long long*)ei)[idx] : ((const int*)ei)[idx];
}

__global__ void hist_kernel(const void* __restrict__ ei, int E) {
    int e = blockIdx.x * blockDim.x + threadIdx.x;
    if (e >= E) return;
    int d = load_edge(ei, (long long)E + e);
    d = min(max(d, 0), N_NODES - 1);
    atomicAdd(&g_deg[d], 1);
}

__global__ void scan1_kernel() {
    __shared__ int warp_sums[32];
    int tid = threadIdx.x, lane = tid & 31, wid = tid >> 5;
    int i = blockIdx.x * SCAN_BLK + tid;
    int v = (i < N_NODES) ? g_deg[i] : 0;
    int s = v;
    #pragma unroll
    for (int d = 1; d < 32; d <<= 1) {
        int t = __shfl_up_sync(0xFFFFFFFFu, s, d);
        if (lane >= d) s += t;
    }
    if (lane == 31) warp_sums[wid] = s;
    __syncthreads();
    if (wid == 0) {
        int ws = warp_sums[lane];
        #pragma unroll
        for (int d = 1; d < 32; d <<= 1) {
            int t = __shfl_up_sync(0xFFFFFFFFu, ws, d);
            if (lane >= d) ws += t;
        }
        warp_sums[lane] = ws;
    }
    __syncthreads();
    int warp_off = (wid == 0) ? 0 : warp_sums[wid - 1];
    if (i < N_NODES) g_off[i] = warp_off + s - v;
    if (tid == SCAN_BLK - 1) g_bsum[blockIdx.x] = warp_off + s;
}

__global__ void scan2_kernel() {
    __shared__ int sh[SCAN_NBLK];
    int tid = threadIdx.x;
    if (tid < SCAN_NBLK) sh[tid] = g_bsum[tid];
    __syncthreads();
    if (tid == 0) {
        int run = 0;
        for (int k = 0; k < SCAN_NBLK; k++) { int t = sh[k]; sh[k] = run; run += t; }
    }
    __syncthreads();
    if (tid < SCAN_NBLK) g_bsum[tid] = sh[tid];
}

__global__ void scan3_kernel() {
    int i = blockIdx.x * SCAN_BLK + threadIdx.x;
    if (i < N_NODES) {
        int o = g_off[i] + g_bsum[blockIdx.x];
        g_off[i] = o;
        g_cur[i] = o;
    }
}

__global__ void fill_kernel(const void* __restrict__ ei, int E) {
    int e = blockIdx.x * blockDim.x + threadIdx.x;
    if (e >= E) return;
    int s = load_edge(ei, e);
    int d = load_edge(ei, (long long)E + e);
    s = min(max(s, 0), N_NODES - 1);
    d = min(max(d, 0), N_NODES - 1);
    int pos = atomicAdd(&g_cur[d], 1);
    if (pos >= 0 && pos < E_MAX) g_srcs[pos] = s;
}

// ---------------------------------------------------------------------------
// Gather-aggregate (identical to R6): one warp per node, fp32 in/out.
// use_h: gather from g_h4 (layer 2) instead of x.
// ---------------------------------------------------------------------------
__global__ __launch_bounds__(512) void aggregate_kernel(
    const float* __restrict__ feat, int use_h)
{
    const float4* f = use_h ? g_h4 : reinterpret_cast<const float4*>(feat);
    int w = (blockIdx.x * blockDim.x + threadIdx.x) >> 5;
    int lane = threadIdx.x & 31;
    if (w >= N_NODES) return;
    int off = g_off[w], deg = g_deg[w];
    float4 a0 = make_float4(0.f, 0.f, 0.f, 0.f);
    float4 a1 = make_float4(0.f, 0.f, 0.f, 0.f);
    for (int j0 = 0; j0 < deg; j0 += 32) {
        int nj = min(32, deg - j0);
        int my = (lane < nj) ? g_srcs[off + j0 + lane] : 0;
        int t = 0;
        for (; t + 2 <= nj; t += 2) {
            int s0 = __shfl_sync(0xFFFFFFFFu, my, t);
            int s1 = __shfl_sync(0xFFFFFFFFu, my, t + 1);
            float4 v0 = f[(size_t)s0 * 32 + lane];
            float4 v1 = f[(size_t)s1 * 32 + lane];
            a0.x += v0.x; a0.y += v0.y; a0.z += v0.z; a0.w += v0.w;
            a1.x += v1.x; a1.y += v1.y; a1.z += v1.z; a1.w += v1.w;
        }
        if (t < nj) {
            int s0 = __shfl_sync(0xFFFFFFFFu, my, t);
            float4 v0 = f[(size_t)s0 * 32 + lane];
            a0.x += v0.x; a0.y += v0.y; a0.z += v0.z; a0.w += v0.w;
        }
    }
    float iv = (deg > 0) ? 1.0f / (float)deg : 0.0f;
    float4 r;
    r.x = (a0.x + a1.x) * iv; r.y = (a0.y + a1.y) * iv;
    r.z = (a0.z + a1.z) * iv; r.w = (a0.w + a1.w) * iv;
    g_agg4[(size_t)w * 32 + lane] = r;
}

// ===========================================================================
// HMMA fused linear: C[N x 128] = [agg | x_or_h] (K=256, fp32) @ B + bias
// B = [Wl;Wr]^T bf16 hi/lo in smem (stride 136, conflict-free ldmatrix).
// A is read fp32 and split to bf16 hi/lo IN REGISTERS per k-step.
// 3 products AhBh + AhBl + AlBh, fp32 accum (AlBl dropped, ~2^-16 rel).
// 256 threads = 8 warps; warp tile 16 rows x 128 cols.
// k-loop "#pragma unroll 1" on purpose: full unroll spilled (R9/R10).
// RELU: writes fp32 h into g_h4; else fp32 to out.
// ===========================================================================
template <bool RELU>
__global__ __launch_bounds__(256, 1) void mma_gemm_kernel(
    const float* __restrict__ Xin,
    const float* __restrict__ Wl, const float* __restrict__ Wr,
    const float* __restrict__ bias, float* __restrict__ outf, int N,
    int use_h_in)
{
    const float* aggp = reinterpret_cast<const float*>(g_agg4);
    const float* xp = use_h_in ? reinterpret_cast<const float*>(g_h4) : Xin;
    float* op = RELU ? reinterpret_cast<float*>(g_h4) : outf;

    extern __shared__ __nv_bfloat16 smem[];
    __nv_bfloat16* b_hi = smem;                 // [256][136]
    __nv_bfloat16* b_lo = smem + 256 * 136;

    int tid = threadIdx.x;
    // Stage B = [Wl;Wr]^T : B[k][n] = (k<128 ? Wl[n][k] : Wr[n][k-128])
    for (int i = tid; i < 256 * 128; i += 256) {
        int k = i >> 7, n = i & 127;
        float wv = (k < 128) ? Wl[n * 128 + k] : Wr[n * 128 + (k - 128)];
        __nv_bfloat16 hb, lb;
        bf_split(wv, hb, lb);
        b_hi[k * 136 + n] = hb;
        b_lo[k * 136 + n] = lb;
    }
    __syncthreads();

    uint32_t sb_hi = smem_u32(b_hi), sb_lo = smem_u32(b_lo);
    int warp = tid >> 5, lane = tid & 31;
    int qp = lane & 3, qr = lane >> 2;           // col-pair / row-in-8
    int lm_k = (lane & 15);
    int lm_n8 = (lane >> 4) << 3;

    int ntiles = (N + 15) >> 4;
    for (int tile = blockIdx.x * 8 + warp; tile < ntiles; tile += gridDim.x * 8) {
        int row0 = tile << 4;
        int rA0 = row0 + qr;
        int rA1 = rA0 + 8;
        if (rA1 >= N) rA1 = N - 1;
        if (rA0 >= N) rA0 = N - 1;

        float d[16][4];
        #pragma unroll
        for (int nt = 0; nt < 16; nt++) {
            int n = nt * 8 + qp * 2;
            float b0v = __ldg(bias + n), b1v = __ldg(bias + n + 1);
            d[nt][0] = b0v; d[nt][1] = b1v; d[nt][2] = b0v; d[nt][3] = b1v;
        }

        #pragma unroll 1
        for (int ks = 0; ks < 16; ks++) {
            int kb = ks * 16;
            // A source: logical cols [kb, kb+16): agg for kb<128, x/h above.
            const float* srcA = (kb < 128) ? aggp : xp;
            int c0 = ((kb < 128) ? kb : kb - 128) + qp * 2;
            const float* r0p = srcA + (size_t)rA0 * NF + c0;
            const float* r1p = srcA + (size_t)rA1 * NF + c0;
            float2 v0 = *reinterpret_cast<const float2*>(r0p);
            float2 v1 = *reinterpret_cast<const float2*>(r1p);
            float2 v2 = *reinterpret_cast<const float2*>(r0p + 8);
            float2 v3 = *reinterpret_cast<const float2*>(r1p + 8);

            uint32_t ah[4], al[4];
            split_pack(v0, ah[0], al[0]);
            split_pack(v1, ah[1], al[1]);
            split_pack(v2, ah[2], al[2]);
            split_pack(v3, ah[3], al[3]);

            uint32_t rowoff = (uint32_t)((kb + lm_k) * 136) * 2u;
            #pragma unroll
            for (int ng = 0; ng < 8; ng++) {
                int n0 = ng * 16;
                uint32_t coloff = (uint32_t)(n0 + lm_n8) * 2u;
                uint32_t bh[4], bl[4];
                ldsm_x4_trans(bh, sb_hi + rowoff + coloff);
                ldsm_x4_trans(bl, sb_lo + rowoff + coloff);
                mma16816(d[ng * 2],     ah, bh[0], bh[1]);
                mma16816(d[ng * 2],     ah, bl[0], bl[1]);
                mma16816(d[ng * 2],     al, bh[0], bh[1]);
                mma16816(d[ng * 2 + 1], ah, bh[2], bh[3]);
                mma16816(d[ng * 2 + 1], ah, bl[2], bl[3]);
                mma16816(d[ng * 2 + 1], al, bh[2], bh[3]);
            }
        }

        // Epilogue: fp32 out (h buffer for layer 1, final out for layer 2).
        int ra = row0 + qr, rb = ra + 8;
        #pragma unroll
        for (int nt = 0; nt < 16; nt++) {
            int n = nt * 8 + qp * 2;
            float v0 = d[nt][0], v1 = d[nt][1], v2 = d[nt][2], v3 = d[nt][3];
            if (RELU) {
                v0 = fmaxf(v0, 0.f); v1 = fmaxf(v1, 0.f);
                v2 = fmaxf(v2, 0.f); v3 = fmaxf(v3, 0.f);
            }
            if (ra < N)
                *reinterpret_cast<float2*>(op + (size_t)ra * NF + n) = make_float2(v0, v1);
            if (rb < N)
                *reinterpret_cast<float2*>(op + (size_t)rb * NF + n) = make_float2(v2, v3);
        }
    }
}

// ---------------------------------------------------------------------------
// init -> hist -> scan -> fill -> agg1 -> gemm1 -> agg2 -> gemm2
// ---------------------------------------------------------------------------
extern "C" void kernel_launch(void* const* d_in, const int* in_sizes, int n_in,
                              void* d_out, int out_size) {
    const float* x = nullptr;
    const void* ei = nullptr;
    const float* w[4] = {nullptr, nullptr, nullptr, nullptr};
    const float* b[2] = {nullptr, nullptr};
    int nw = 0, nb = 0, E = 0, N = N_NODES;

    for (int i = 0; i < n_in; i++) {
        int sz = in_sizes[i];
        if (sz == N_NODES * NF) {
            x = (const float*)d_in[i];
        } else if (sz == NF * NF) {
            if (nw < 4) w[nw++] = (const float*)d_in[i];
        } else if (sz == NF) {
            if (nb < 2) b[nb++] = (const float*)d_in[i];
        } else {
            ei = d_in[i];
            E = sz / 2;
        }
    }
    if (E > E_MAX) E = E_MAX;
    const float *w1l = w[0], *w1r = w[1], *w2l = w[2], *w2r = w[3];
    const float *b1 = b[0], *b2 = b[1];
    float* out = (float*)d_out;

    size_t gemm_smem = (size_t)2 * 256 * 136 * sizeof(__nv_bfloat16);  // 136 KB
    cudaFuncSetAttribute(mma_gemm_kernel<true>,  cudaFuncAttributeMaxDynamicSharedMemorySize, (int)gemm_smem);
    cudaFuncSetAttribute(mma_gemm_kernel<false>, cudaFuncAttributeMaxDynamicSharedMemorySize, (int)gemm_smem);

    int agg_grid = (N_NODES * 32 + 511) / 512;

    init_kernel<<<(N_NODES + 511) / 512, 512>>>((const int*)ei);
    if (E > 0) hist_kernel<<<(E + 511) / 512, 512>>>(ei, E);
    scan1_kernel<<<SCAN_NBLK, SCAN_BLK>>>();
    scan2_kernel<<<1, 128>>>();
    scan3_kernel<<<SCAN_NBLK, SCAN_BLK>>>();
    if (E > 0) fill_kernel<<<(E + 511) / 512, 512>>>(ei, E);

    // Layer 1: [agg(x) | x] -> h (fp32, g_h4)
    aggregate_kernel<<<agg_grid, 512>>>(x, 0);
    mma_gemm_kernel<true><<<296, 256, gemm_smem>>>(x, w1l, w1r, b1, out, N, 0);

    // Layer 2: [agg(h) | h] -> out
    aggregate_kernel<<<agg_grid, 512>>>(x, 1);
    mma_gemm_kernel<false><<<296, 256, gemm_smem>>>(x, w2l, w2r, b2, out, N, 1);
}

// round 13
// speedup vs baseline: 1.4497x; 1.0048x over previous
#include <cuda_runtime.h>
#include <cuda_bf16.h>
#include <cstdint>

#define NF 128
#define N_NODES 100000
#define E_MAX 2000000
#define SCAN_BLK 1024
#define SCAN_NBLK ((N_NODES + SCAN_BLK - 1) / SCAN_BLK)   // 98

// Scratch: static device globals. Total ~112MB — same footprint as the last
// PASSING round (R6). (R9-R11 declared ~214MB of globals and tripped the
// harness alloc-guard with a constant 256MiB arena delta.)
__device__ float4 g_agg4[(size_t)N_NODES * NF / 4];   // 51.2 MB fp32 mean rows
__device__ float4 g_h4[(size_t)N_NODES * NF / 4];     // 51.2 MB fp32 hidden
__device__ int g_deg[N_NODES];
__device__ int g_off[N_NODES];
__device__ int g_cur[N_NODES];
__device__ int g_srcs[E_MAX];
__device__ int g_bsum[SCAN_NBLK];
__device__ int g_is64;

// ---------------------------------------------------------------------------
// helpers
// ---------------------------------------------------------------------------
__device__ __forceinline__ uint32_t smem_u32(const void* p) {
    uint32_t a;
    asm("{ .reg .u64 t; cvta.to.shared.u64 t, %1; cvt.u32.u64 %0, t; }"
        : "=r"(a) : "l"(p));
    return a;
}

__device__ __forceinline__ uint32_t pack2(__nv_bfloat16 a, __nv_bfloat16 b) {
    __nv_bfloat162 t = __halves2bfloat162(a, b);   // a = low half
    return *reinterpret_cast<uint32_t*>(&t);
}

__device__ __forceinline__ void bf_split(float v, __nv_bfloat16& h, __nv_bfloat16& l) {
    h = __float2bfloat16(v);
    l = __float2bfloat16(v - __bfloat162float(h));
}

// fp32 pair -> bf16 hi-pack + lo-pack
__device__ __forceinline__ void split_pack(float2 v, uint32_t& hp, uint32_t& lp) {
    __nv_bfloat16 h0, l0, h1, l1;
    bf_split(v.x, h0, l0);
    bf_split(v.y, h1, l1);
    hp = pack2(h0, h1);
    lp = pack2(l0, l1);
}

__device__ __forceinline__ void mma16816(float* d, const uint32_t* a,
                                         uint32_t b0, uint32_t b1) {
    asm volatile(
        "mma.sync.aligned.m16n8k16.row.col.f32.bf16.bf16.f32 "
        "{%0,%1,%2,%3}, {%4,%5,%6,%7}, {%8,%9}, {%0,%1,%2,%3};"
        : "+f"(d[0]), "+f"(d[1]), "+f"(d[2]), "+f"(d[3])
        : "r"(a[0]), "r"(a[1]), "r"(a[2]), "r"(a[3]), "r"(b0), "r"(b1));
}

__device__ __forceinline__ void ldsm_x4_trans(uint32_t* r, uint32_t addr) {
    asm volatile(
        "ldmatrix.sync.aligned.m8n8.x4.trans.shared.b16 {%0,%1,%2,%3}, [%4];"
        : "=r"(r[0]), "=r"(r[1]), "=r"(r[2]), "=r"(r[3]) : "r"(addr));
}

// ===========================================================================
// Preprocessing (identical to R6 — last fully-passing version)
// ===========================================================================
__global__ void init_kernel(const int* __restrict__ ei_words) {
    int i = blockIdx.x * blockDim.x + threadIdx.x;
    if (i < N_NODES) g_deg[i] = 0;
    if (i == 0) {
        int is64 = 1;
        #pragma unroll
        for (int k = 0; k < 64; k++)
            if (ei_words[2 * k + 1] != 0) { is64 = 0; break; }
        g_is64 = is64;
    }
}

__device__ __forceinline__ int load_edge(const void* ei, long long idx) {
    return g_is64 ? (int)((const long long*)ei)[idx] : ((const int*)ei)[idx];
}

__global__ void hist_kernel(const void* __restrict__ ei, int E) {
    int e = blockIdx.x * blockDim.x + threadIdx.x;
    if (e >= E) return;
    int d = load_edge(ei, (long long)E + e);
    d = min(max(d, 0), N_NODES - 1);
    atomicAdd(&g_deg[d], 1);
}

__global__ void scan1_kernel() {
    __shared__ int warp_sums[32];
    int tid = threadIdx.x, lane = tid & 31, wid = tid >> 5;
    int i = blockIdx.x * SCAN_BLK + tid;
    int v = (i < N_NODES) ? g_deg[i] : 0;
    int s = v;
    #pragma unroll
    for (int d = 1; d < 32; d <<= 1) {
        int t = __shfl_up_sync(0xFFFFFFFFu, s, d);
        if (lane >= d) s += t;
    }
    if (lane == 31) warp_sums[wid] = s;
    __syncthreads();
    if (wid == 0) {
        int ws = warp_sums[lane];
        #pragma unroll
        for (int d = 1; d < 32; d <<= 1) {
            int t = __shfl_up_sync(0xFFFFFFFFu, ws, d);
            if (lane >= d) ws += t;
        }
        warp_sums[lane] = ws;
    }
    __syncthreads();
    int warp_off = (wid == 0) ? 0 : warp_sums[wid - 1];
    if (i < N_NODES) g_off[i] = warp_off + s - v;
    if (tid == SCAN_BLK - 1) g_bsum[blockIdx.x] = warp_off + s;
}

__global__ void scan2_kernel() {
    __shared__ int sh[SCAN_NBLK];
    int tid = threadIdx.x;
    if (tid < SCAN_NBLK) sh[tid] = g_bsum[tid];
    __syncthreads();
    if (tid == 0) {
        int run = 0;
        for (int k = 0; k < SCAN_NBLK; k++) { int t = sh[k]; sh[k] = run; run += t; }
    }
    __syncthreads();
    if (tid < SCAN_NBLK) g_bsum[tid] = sh[tid];
}

__global__ void scan3_kernel() {
    int i = blockIdx.x * SCAN_BLK + threadIdx.x;
    if (i < N_NODES) {
        int o = g_off[i] + g_bsum[blockIdx.x];
        g_off[i] = o;
        g_cur[i] = o;
    }
}

__global__ void fill_kernel(const void* __restrict__ ei, int E) {
    int e = blockIdx.x * blockDim.x + threadIdx.x;
    if (e >= E) return;
    int s = load_edge(ei, e);
    int d = load_edge(ei, (long long)E + e);
    s = min(max(s, 0), N_NODES - 1);
    d = min(max(d, 0), N_NODES - 1);
    int pos = atomicAdd(&g_cur[d], 1);
    if (pos >= 0 && pos < E_MAX) g_srcs[pos] = s;
}

// ---------------------------------------------------------------------------
// Gather-aggregate (identical to R6): one warp per node, fp32 in/out.
// use_h: gather from g_h4 (layer 2) instead of x.
// ---------------------------------------------------------------------------
__global__ __launch_bounds__(512) void aggregate_kernel(
    const float* __restrict__ feat, int use_h)
{
    const float4* f = use_h ? g_h4 : reinterpret_cast<const float4*>(feat);
    int w = (blockIdx.x * blockDim.x + threadIdx.x) >> 5;
    int lane = threadIdx.x & 31;
    if (w >= N_NODES) return;
    int off = g_off[w], deg = g_deg[w];
    float4 a0 = make_float4(0.f, 0.f, 0.f, 0.f);
    float4 a1 = make_float4(0.f, 0.f, 0.f, 0.f);
    for (int j0 = 0; j0 < deg; j0 += 32) {
        int nj = min(32, deg - j0);
        int my = (lane < nj) ? g_srcs[off + j0 + lane] : 0;
        int t = 0;
        for (; t + 2 <= nj; t += 2) {
            int s0 = __shfl_sync(0xFFFFFFFFu, my, t);
            int s1 = __shfl_sync(0xFFFFFFFFu, my, t + 1);
            float4 v0 = f[(size_t)s0 * 32 + lane];
            float4 v1 = f[(size_t)s1 * 32 + lane];
            a0.x += v0.x; a0.y += v0.y; a0.z += v0.z; a0.w += v0.w;
            a1.x += v1.x; a1.y += v1.y; a1.z += v1.z; a1.w += v1.w;
        }
        if (t < nj) {
            int s0 = __shfl_sync(0xFFFFFFFFu, my, t);
            float4 v0 = f[(size_t)s0 * 32 + lane];
            a0.x += v0.x; a0.y += v0.y; a0.z += v0.z; a0.w += v0.w;
        }
    }
    float iv = (deg > 0) ? 1.0f / (float)deg : 0.0f;
    float4 r;
    r.x = (a0.x + a1.x) * iv; r.y = (a0.y + a1.y) * iv;
    r.z = (a0.z + a1.z) * iv; r.w = (a0.w + a1.w) * iv;
    g_agg4[(size_t)w * 32 + lane] = r;
}

// ===========================================================================
// HMMA fused linear: C[N x 128] = [agg | x_or_h] (K=256, fp32) @ B + bias
// B = [Wl;Wr]^T bf16 hi/lo in smem (stride 136, conflict-free ldmatrix).
// A is read fp32 and split to bf16 hi/lo IN REGISTERS per k-step.
// 3 products AhBh + AhBl + AlBh, fp32 accum (AlBl dropped, ~2^-16 rel).
// 256 threads = 8 warps; warp tile 16 rows x 128 cols.
// k-loop "#pragma unroll 1" on purpose: full unroll spilled (R9/R10).
// RELU: writes fp32 h into g_h4; else fp32 to out.
// ===========================================================================
template <bool RELU>
__global__ __launch_bounds__(256, 1) void mma_gemm_kernel(
    const float* __restrict__ Xin,
    const float* __restrict__ Wl, const float* __restrict__ Wr,
    const float* __restrict__ bias, float* __restrict__ outf, int N,
    int use_h_in)
{
    const float* aggp = reinterpret_cast<const float*>(g_agg4);
    const float* xp = use_h_in ? reinterpret_cast<const float*>(g_h4) : Xin;
    float* op = RELU ? reinterpret_cast<float*>(g_h4) : outf;

    extern __shared__ __nv_bfloat16 smem[];
    __nv_bfloat16* b_hi = smem;                 // [256][136]
    __nv_bfloat16* b_lo = smem + 256 * 136;

    int tid = threadIdx.x;
    // Stage B = [Wl;Wr]^T : B[k][n] = (k<128 ? Wl[n][k] : Wr[n][k-128])
    for (int i = tid; i < 256 * 128; i += 256) {
        int k = i >> 7, n = i & 127;
        float wv = (k < 128) ? Wl[n * 128 + k] : Wr[n * 128 + (k - 128)];
        __nv_bfloat16 hb, lb;
        bf_split(wv, hb, lb);
        b_hi[k * 136 + n] = hb;
        b_lo[k * 136 + n] = lb;
    }
    __syncthreads();

    uint32_t sb_hi = smem_u32(b_hi), sb_lo = smem_u32(b_lo);
    int warp = tid >> 5, lane = tid & 31;
    int qp = lane & 3, qr = lane >> 2;           // col-pair / row-in-8
    int lm_k = (lane & 15);
    int lm_n8 = (lane >> 4) << 3;

    int ntiles = (N + 15) >> 4;
    for (int tile = blockIdx.x * 8 + warp; tile < ntiles; tile += gridDim.x * 8) {
        int row0 = tile << 4;
        int rA0 = row0 + qr;
        int rA1 = rA0 + 8;
        if (rA1 >= N) rA1 = N - 1;
        if (rA0 >= N) rA0 = N - 1;

        float d[16][4];
        #pragma unroll
        for (int nt = 0; nt < 16; nt++) {
            int n = nt * 8 + qp * 2;
            float b0v = __ldg(bias + n), b1v = __ldg(bias + n + 1);
            d[nt][0] = b0v; d[nt][1] = b1v; d[nt][2] = b0v; d[nt][3] = b1v;
        }

        #pragma unroll 1
        for (int ks = 0; ks < 16; ks++) {
            int kb = ks * 16;
            // A source: logical cols [kb, kb+16): agg for kb<128, x/h above.
            const float* srcA = (kb < 128) ? aggp : xp;
            int c0 = ((kb < 128) ? kb : kb - 128) + qp * 2;
            const float* r0p = srcA + (size_t)rA0 * NF + c0;
            const float* r1p = srcA + (size_t)rA1 * NF + c0;
            float2 v0 = *reinterpret_cast<const float2*>(r0p);
            float2 v1 = *reinterpret_cast<const float2*>(r1p);
            float2 v2 = *reinterpret_cast<const float2*>(r0p + 8);
            float2 v3 = *reinterpret_cast<const float2*>(r1p + 8);

            uint32_t ah[4], al[4];
            split_pack(v0, ah[0], al[0]);
            split_pack(v1, ah[1], al[1]);
            split_pack(v2, ah[2], al[2]);
            split_pack(v3, ah[3], al[3]);

            uint32_t rowoff = (uint32_t)((kb + lm_k) * 136) * 2u;
            #pragma unroll
            for (int ng = 0; ng < 8; ng++) {
                int n0 = ng * 16;
                uint32_t coloff = (uint32_t)(n0 + lm_n8) * 2u;
                uint32_t bh[4], bl[4];
                ldsm_x4_trans(bh, sb_hi + rowoff + coloff);
                ldsm_x4_trans(bl, sb_lo + rowoff + coloff);
                mma16816(d[ng * 2],     ah, bh[0], bh[1]);
                mma16816(d[ng * 2],     ah, bl[0], bl[1]);
                mma16816(d[ng * 2],     al, bh[0], bh[1]);
                mma16816(d[ng * 2 + 1], ah, bh[2], bh[3]);
                mma16816(d[ng * 2 + 1], ah, bl[2], bl[3]);
                mma16816(d[ng * 2 + 1], al, bh[2], bh[3]);
            }
        }

        // Epilogue: fp32 out (h buffer for layer 1, final out for layer 2).
        int ra = row0 + qr, rb = ra + 8;
        #pragma unroll
        for (int nt = 0; nt < 16; nt++) {
            int n = nt * 8 + qp * 2;
            float v0 = d[nt][0], v1 = d[nt][1], v2 = d[nt][2], v3 = d[nt][3];
            if (RELU) {
                v0 = fmaxf(v0, 0.f); v1 = fmaxf(v1, 0.f);
                v2 = fmaxf(v2, 0.f); v3 = fmaxf(v3, 0.f);
            }
            if (ra < N)
                *reinterpret_cast<float2*>(op + (size_t)ra * NF + n) = make_float2(v0, v1);
            if (rb < N)
                *reinterpret_cast<float2*>(op + (size_t)rb * NF + n) = make_float2(v2, v3);
        }
    }
}

// ---------------------------------------------------------------------------
// init -> hist -> scan -> fill -> agg1 -> gemm1 -> agg2 -> gemm2
// ---------------------------------------------------------------------------
extern "C" void kernel_launch(void* const* d_in, const int* in_sizes, int n_in,
                              void* d_out, int out_size) {
    const float* x = nullptr;
    const void* ei = nullptr;
    const float* w[4] = {nullptr, nullptr, nullptr, nullptr};
    const float* b[2] = {nullptr, nullptr};
    int nw = 0, nb = 0, E = 0, N = N_NODES;

    for (int i = 0; i < n_in; i++) {
        int sz = in_sizes[i];
        if (sz == N_NODES * NF) {
            x = (const float*)d_in[i];
        } else if (sz == NF * NF) {
            if (nw < 4) w[nw++] = (const float*)d_in[i];
        } else if (sz == NF) {
            if (nb < 2) b[nb++] = (const float*)d_in[i];
        } else {
            ei = d_in[i];
            E = sz / 2;
        }
    }
    if (E > E_MAX) E = E_MAX;
    const float *w1l = w[0], *w1r = w[1], *w2l = w[2], *w2r = w[3];
    const float *b1 = b[0], *b2 = b[1];
    float* out = (float*)d_out;

    size_t gemm_smem = (size_t)2 * 256 * 136 * sizeof(__nv_bfloat16);  // 136 KB
    cudaFuncSetAttribute(mma_gemm_kernel<true>,  cudaFuncAttributeMaxDynamicSharedMemorySize, (int)gemm_smem);
    cudaFuncSetAttribute(mma_gemm_kernel<false>, cudaFuncAttributeMaxDynamicSharedMemorySize, (int)gemm_smem);

    int agg_grid = (N_NODES * 32 + 511) / 512;

    init_kernel<<<(N_NODES + 511) / 512, 512>>>((const int*)ei);
    if (E > 0) hist_kernel<<<(E + 511) / 512, 512>>>(ei, E);
    scan1_kernel<<<SCAN_NBLK, SCAN_BLK>>>();
    scan2_kernel<<<1, 128>>>();
    scan3_kernel<<<SCAN_NBLK, SCAN_BLK>>>();
    if (E > 0) fill_kernel<<<(E + 511) / 512, 512>>>(ei, E);

    // Layer 1: [agg(x) | x] -> h (fp32, g_h4)
    aggregate_kernel<<<agg_grid, 512>>>(x, 0);
    mma_gemm_kernel<true><<<296, 256, gemm_smem>>>(x, w1l, w1r, b1, out, N, 0);

    // Layer 2: [agg(h) | h] -> out
    aggregate_kernel<<<agg_grid, 512>>>(x, 1);
    mma_gemm_kernel<false><<<296, 256, gemm_smem>>>(x, w2l, w2r, b2, out, N, 1);
}

// round 14
// speedup vs baseline: 1.4507x; 1.0007x over previous
#include <cuda_runtime.h>
#include <cuda_bf16.h>
#include <cstdint>

#define NF 128
#define N_NODES 100000
#define E_MAX 2000000
#define SCAN_BLK 1024
#define SCAN_NBLK ((N_NODES + SCAN_BLK - 1) / SCAN_BLK)   // 98

// Scratch: static device globals. Total ~112MB — same footprint as the last
// PASSING round (R6). (R9-R11 declared ~214MB of globals and tripped the
// harness alloc-guard with a constant 256MiB arena delta.)
__device__ float4 g_agg4[(size_t)N_NODES * NF / 4];   // 51.2 MB fp32 mean rows
__device__ float4 g_h4[(size_t)N_NODES * NF / 4];     // 51.2 MB fp32 hidden
__device__ int g_deg[N_NODES];
__device__ int g_off[N_NODES];
__device__ int g_cur[N_NODES];
__device__ int g_srcs[E_MAX];
__device__ int g_bsum[SCAN_NBLK];
__device__ int g_is64;

// ---------------------------------------------------------------------------
// helpers
// ---------------------------------------------------------------------------
__device__ __forceinline__ uint32_t smem_u32(const void* p) {
    uint32_t a;
    asm("{ .reg .u64 t; cvta.to.shared.u64 t, %1; cvt.u32.u64 %0, t; }"
        : "=r"(a) : "l"(p));
    return a;
}

__device__ __forceinline__ uint32_t pack2(__nv_bfloat16 a, __nv_bfloat16 b) {
    __nv_bfloat162 t = __halves2bfloat162(a, b);   // a = low half
    return *reinterpret_cast<uint32_t*>(&t);
}

__device__ __forceinline__ void bf_split(float v, __nv_bfloat16& h, __nv_bfloat16& l) {
    h = __float2bfloat16(v);
    l = __float2bfloat16(v - __bfloat162float(h));
}

// fp32 pair -> bf16 hi-pack + lo-pack
__device__ __forceinline__ void split_pack(float2 v, uint32_t& hp, uint32_t& lp) {
    __nv_bfloat16 h0, l0, h1, l1;
    bf_split(v.x, h0, l0);
    bf_split(v.y, h1, l1);
    hp = pack2(h0, h1);
    lp = pack2(l0, l1);
}

__device__ __forceinline__ void mma16816(float* d, const uint32_t* a,
                                         uint32_t b0, uint32_t b1) {
    asm volatile(
        "mma.sync.aligned.m16n8k16.row.col.f32.bf16.bf16.f32 "
        "{%0,%1,%2,%3}, {%4,%5,%6,%7}, {%8,%9}, {%0,%1,%2,%3};"
        : "+f"(d[0]), "+f"(d[1]), "+f"(d[2]), "+f"(d[3])
        : "r"(a[0]), "r"(a[1]), "r"(a[2]), "r"(a[3]), "r"(b0), "r"(b1));
}

__device__ __forceinline__ void ldsm_x4_trans(uint32_t* r, uint32_t addr) {
    asm volatile(
        "ldmatrix.sync.aligned.m8n8.x4.trans.shared.b16 {%0,%1,%2,%3}, [%4];"
        : "=r"(r[0]), "=r"(r[1]), "=r"(r[2]), "=r"(r[3]) : "r"(addr));
}

// ===========================================================================
// Preprocessing (identical to R6 — last fully-passing version)
// ===========================================================================
__global__ void init_kernel(const int* __restrict__ ei_words) {
    int i = blockIdx.x * blockDim.x + threadIdx.x;
    if (i < N_NODES) g_deg[i] = 0;
    if (i == 0) {
        int is64 = 1;
        #pragma unroll
        for (int k = 0; k < 64; k++)
            if (ei_words[2 * k + 1] != 0) { is64 = 0; break; }
        g_is64 = is64;
    }
}

__device__ __forceinline__ int load_edge(const void* ei, long long idx) {
    return g_is64 ? (int)((const long long*)ei)[idx] : ((const int*)ei)[idx];
}

__global__ void hist_kernel(const void* __restrict__ ei, int E) {
    int e = blockIdx.x * blockDim.x + threadIdx.x;
    if (e >= E) return;
    int d = load_edge(ei, (long long)E + e);
    d = min(max(d, 0), N_NODES - 1);
    atomicAdd(&g_deg[d], 1);
}

__global__ void scan1_kernel() {
    __shared__ int warp_sums[32];
    int tid = threadIdx.x, lane = tid & 31, wid = tid >> 5;
    int i = blockIdx.x * SCAN_BLK + tid;
    int v = (i < N_NODES) ? g_deg[i] : 0;
    int s = v;
    #pragma unroll
    for (int d = 1; d < 32; d <<= 1) {
        int t = __shfl_up_sync(0xFFFFFFFFu, s, d);
        if (lane >= d) s += t;
    }
    if (lane == 31) warp_sums[wid] = s;
    __syncthreads();
    if (wid == 0) {
        int ws = warp_sums[lane];
        #pragma unroll
        for (int d = 1; d < 32; d <<= 1) {
            int t = __shfl_up_sync(0xFFFFFFFFu, ws, d);
            if (lane >= d) ws += t;
        }
        warp_sums[lane] = ws;
    }
    __syncthreads();
    int warp_off = (wid == 0) ? 0 : warp_sums[wid - 1];
    if (i < N_NODES) g_off[i] = warp_off + s - v;
    if (tid == SCAN_BLK - 1) g_bsum[blockIdx.x] = warp_off + s;
}

__global__ void scan2_kernel() {
    __shared__ int sh[SCAN_NBLK];
    int tid = threadIdx.x;
    if (tid < SCAN_NBLK) sh[tid] = g_bsum[tid];
    __syncthreads();
    if (tid == 0) {
        int run = 0;
        for (int k = 0; k < SCAN_NBLK; k++) { int t = sh[k]; sh[k] = run; run += t; }
    }
    __syncthreads();
    if (tid < SCAN_NBLK) g_bsum[tid] = sh[tid];
}

__global__ void scan3_kernel() {
    int i = blockIdx.x * SCAN_BLK + threadIdx.x;
    if (i < N_NODES) {
        int o = g_off[i] + g_bsum[blockIdx.x];
        g_off[i] = o;
        g_cur[i] = o;
    }
}

__global__ void fill_kernel(const void* __restrict__ ei, int E) {
    int e = blockIdx.x * blockDim.x + threadIdx.x;
    if (e >= E) return;
    int s = load_edge(ei, e);
    int d = load_edge(ei, (long long)E + e);
    s = min(max(s, 0), N_NODES - 1);
    d = min(max(d, 0), N_NODES - 1);
    int pos = atomicAdd(&g_cur[d], 1);
    if (pos >= 0 && pos < E_MAX) g_srcs[pos] = s;
}

// ---------------------------------------------------------------------------
// Gather-aggregate (identical to R6): one warp per node, fp32 in/out.
// use_h: gather from g_h4 (layer 2) instead of x.
// ---------------------------------------------------------------------------
__global__ __launch_bounds__(512) void aggregate_kernel(
    const float* __restrict__ feat, int use_h)
{
    const float4* f = use_h ? g_h4 : reinterpret_cast<const float4*>(feat);
    int w = (blockIdx.x * blockDim.x + threadIdx.x) >> 5;
    int lane = threadIdx.x & 31;
    if (w >= N_NODES) return;
    int off = g_off[w], deg = g_deg[w];
    float4 a0 = make_float4(0.f, 0.f, 0.f, 0.f);
    float4 a1 = make_float4(0.f, 0.f, 0.f, 0.f);
    for (int j0 = 0; j0 < deg; j0 += 32) {
        int nj = min(32, deg - j0);
        int my = (lane < nj) ? g_srcs[off + j0 + lane] : 0;
        int t = 0;
        for (; t + 2 <= nj; t += 2) {
            int s0 = __shfl_sync(0xFFFFFFFFu, my, t);
            int s1 = __shfl_sync(0xFFFFFFFFu, my, t + 1);
            float4 v0 = f[(size_t)s0 * 32 + lane];
            float4 v1 = f[(size_t)s1 * 32 + lane];
            a0.x += v0.x; a0.y += v0.y; a0.z += v0.z; a0.w += v0.w;
            a1.x += v1.x; a1.y += v1.y; a1.z += v1.z; a1.w += v1.w;
        }
        if (t < nj) {
            int s0 = __shfl_sync(0xFFFFFFFFu, my, t);
            float4 v0 = f[(size_t)s0 * 32 + lane];
            a0.x += v0.x; a0.y += v0.y; a0.z += v0.z; a0.w += v0.w;
        }
    }
    float iv = (deg > 0) ? 1.0f / (float)deg : 0.0f;
    float4 r;
    r.x = (a0.x + a1.x) * iv; r.y = (a0.y + a1.y) * iv;
    r.z = (a0.z + a1.z) * iv; r.w = (a0.w + a1.w) * iv;
    g_agg4[(size_t)w * 32 + lane] = r;
}

// ===========================================================================
// HMMA fused linear: C[N x 128] = [agg | x_or_h] (K=256, fp32) @ B + bias
// B = [Wl;Wr]^T bf16 hi/lo in smem (stride 136, conflict-free ldmatrix).
// A is read fp32 and split to bf16 hi/lo IN REGISTERS per k-step.
// 3 products AhBh + AhBl + AlBh, fp32 accum (AlBl dropped, ~2^-16 rel).
// 256 threads = 8 warps; warp tile 16 rows x 128 cols.
// k-loop "#pragma unroll 1" on purpose: full unroll spilled (R9/R10).
// RELU: writes fp32 h into g_h4; else fp32 to out.
// ===========================================================================
template <bool RELU>
__global__ __launch_bounds__(256, 1) void mma_gemm_kernel(
    const float* __restrict__ Xin,
    const float* __restrict__ Wl, const float* __restrict__ Wr,
    const float* __restrict__ bias, float* __restrict__ outf, int N,
    int use_h_in)
{
    const float* aggp = reinterpret_cast<const float*>(g_agg4);
    const float* xp = use_h_in ? reinterpret_cast<const float*>(g_h4) : Xin;
    float* op = RELU ? reinterpret_cast<float*>(g_h4) : outf;

    extern __shared__ __nv_bfloat16 smem[];
    __nv_bfloat16* b_hi = smem;                 // [256][136]
    __nv_bfloat16* b_lo = smem + 256 * 136;

    int tid = threadIdx.x;
    // Stage B = [Wl;Wr]^T : B[k][n] = (k<128 ? Wl[n][k] : Wr[n][k-128])
    for (int i = tid; i < 256 * 128; i += 256) {
        int k = i >> 7, n = i & 127;
        float wv = (k < 128) ? Wl[n * 128 + k] : Wr[n * 128 + (k - 128)];
        __nv_bfloat16 hb, lb;
        bf_split(wv, hb, lb);
        b_hi[k * 136 + n] = hb;
        b_lo[k * 136 + n] = lb;
    }
    __syncthreads();

    uint32_t sb_hi = smem_u32(b_hi), sb_lo = smem_u32(b_lo);
    int warp = tid >> 5, lane = tid & 31;
    int qp = lane & 3, qr = lane >> 2;           // col-pair / row-in-8
    int lm_k = (lane & 15);
    int lm_n8 = (lane >> 4) << 3;

    int ntiles = (N + 15) >> 4;
    for (int tile = blockIdx.x * 8 + warp; tile < ntiles; tile += gridDim.x * 8) {
        int row0 = tile << 4;
        int rA0 = row0 + qr;
        int rA1 = rA0 + 8;
        if (rA1 >= N) rA1 = N - 1;
        if (rA0 >= N) rA0 = N - 1;

        float d[16][4];
        #pragma unroll
        for (int nt = 0; nt < 16; nt++) {
            int n = nt * 8 + qp * 2;
            float b0v = __ldg(bias + n), b1v = __ldg(bias + n + 1);
            d[nt][0] = b0v; d[nt][1] = b1v; d[nt][2] = b0v; d[nt][3] = b1v;
        }

        #pragma unroll 1
        for (int ks = 0; ks < 16; ks++) {
            int kb = ks * 16;
            // A source: logical cols [kb, kb+16): agg for kb<128, x/h above.
            const float* srcA = (kb < 128) ? aggp : xp;
            int c0 = ((kb < 128) ? kb : kb - 128) + qp * 2;
            const float* r0p = srcA + (size_t)rA0 * NF + c0;
            const float* r1p = srcA + (size_t)rA1 * NF + c0;
            float2 v0 = *reinterpret_cast<const float2*>(r0p);
            float2 v1 = *reinterpret_cast<const float2*>(r1p);
            float2 v2 = *reinterpret_cast<const float2*>(r0p + 8);
            float2 v3 = *reinterpret_cast<const float2*>(r1p + 8);

            uint32_t ah[4], al[4];
            split_pack(v0, ah[0], al[0]);
            split_pack(v1, ah[1], al[1]);
            split_pack(v2, ah[2], al[2]);
            split_pack(v3, ah[3], al[3]);

            uint32_t rowoff = (uint32_t)((kb + lm_k) * 136) * 2u;
            #pragma unroll
            for (int ng = 0; ng < 8; ng++) {
                int n0 = ng * 16;
                uint32_t coloff = (uint32_t)(n0 + lm_n8) * 2u;
                uint32_t bh[4], bl[4];
                ldsm_x4_trans(bh, sb_hi + rowoff + coloff);
                ldsm_x4_trans(bl, sb_lo + rowoff + coloff);
                mma16816(d[ng * 2],     ah, bh[0], bh[1]);
                mma16816(d[ng * 2],     ah, bl[0], bl[1]);
                mma16816(d[ng * 2],     al, bh[0], bh[1]);
                mma16816(d[ng * 2 + 1], ah, bh[2], bh[3]);
                mma16816(d[ng * 2 + 1], ah, bl[2], bl[3]);
                mma16816(d[ng * 2 + 1], al, bh[2], bh[3]);
            }
        }

        // Epilogue: fp32 out (h buffer for layer 1, final out for layer 2).
        int ra = row0 + qr, rb = ra + 8;
        #pragma unroll
        for (int nt = 0; nt < 16; nt++) {
            int n = nt * 8 + qp * 2;
            float v0 = d[nt][0], v1 = d[nt][1], v2 = d[nt][2], v3 = d[nt][3];
            if (RELU) {
                v0 = fmaxf(v0, 0.f); v1 = fmaxf(v1, 0.f);
                v2 = fmaxf(v2, 0.f); v3 = fmaxf(v3, 0.f);
            }
            if (ra < N)
                *reinterpret_cast<float2*>(op + (size_t)ra * NF + n) = make_float2(v0, v1);
            if (rb < N)
                *reinterpret_cast<float2*>(op + (size_t)rb * NF + n) = make_float2(v2, v3);
        }
    }
}

// ---------------------------------------------------------------------------
// init -> hist -> scan -> fill -> agg1 -> gemm1 -> agg2 -> gemm2
// ---------------------------------------------------------------------------
extern "C" void kernel_launch(void* const* d_in, const int* in_sizes, int n_in,
                              void* d_out, int out_size) {
    const float* x = nullptr;
    const void* ei = nullptr;
    const float* w[4] = {nullptr, nullptr, nullptr, nullptr};
    const float* b[2] = {nullptr, nullptr};
    int nw = 0, nb = 0, E = 0, N = N_NODES;

    for (int i = 0; i < n_in; i++) {
        int sz = in_sizes[i];
        if (sz == N_NODES * NF) {
            x = (const float*)d_in[i];
        } else if (sz == NF * NF) {
            if (nw < 4) w[nw++] = (const float*)d_in[i];
        } else if (sz == NF) {
            if (nb < 2) b[nb++] = (const float*)d_in[i];
        } else {
            ei = d_in[i];
            E = sz / 2;
        }
    }
    if (E > E_MAX) E = E_MAX;
    const float *w1l = w[0], *w1r = w[1], *w2l = w[2], *w2r = w[3];
    const float *b1 = b[0], *b2 = b[1];
    float* out = (float*)d_out;

    size_t gemm_smem = (size_t)2 * 256 * 136 * sizeof(__nv_bfloat16);  // 136 KB
    cudaFuncSetAttribute(mma_gemm_kernel<true>,  cudaFuncAttributeMaxDynamicSharedMemorySize, (int)gemm_smem);
    cudaFuncSetAttribute(mma_gemm_kernel<false>, cudaFuncAttributeMaxDynamicSharedMemorySize, (int)gemm_smem);

    int agg_grid = (N_NODES * 32 + 511) / 512;

    init_kernel<<<(N_NODES + 511) / 512, 512>>>((const int*)ei);
    if (E > 0) hist_kernel<<<(E + 511) / 512, 512>>>(ei, E);
    scan1_kernel<<<SCAN_NBLK, SCAN_BLK>>>();
    scan2_kernel<<<1, 128>>>();
    scan3_kernel<<<SCAN_NBLK, SCAN_BLK>>>();
    if (E > 0) fill_kernel<<<(E + 511) / 512, 512>>>(ei, E);

    // Layer 1: [agg(x) | x] -> h (fp32, g_h4)
    aggregate_kernel<<<agg_grid, 512>>>(x, 0);
    mma_gemm_kernel<true><<<296, 256, gemm_smem>>>(x, w1l, w1r, b1, out, N, 0);

    // Layer 2: [agg(h) | h] -> out
    aggregate_kernel<<<agg_grid, 512>>>(x, 1);
    mma_gemm_kernel<false><<<296, 256, gemm_smem>>>(x, w2l, w2r, b2, out, N, 1);
}

// round 15
// speedup vs baseline: 1.5251x; 1.0513x over previous
#include <cuda_runtime.h>
#include <cuda_bf16.h>
#include <cstdint>

#define NF 128
#define N_NODES 100000
#define E_MAX 2000000
#define SCAN_BLK 1024
#define SCAN_NBLK ((N_NODES + SCAN_BLK - 1) / SCAN_BLK)   // 98

// Scratch: static device globals, ~112MB total (proven safe footprint;
// >=214MB of globals trips the harness alloc-guard arena).
__device__ float4 g_agg4[(size_t)N_NODES * NF / 4];   // 51.2 MB fp32 mean rows
__device__ float4 g_h4[(size_t)N_NODES * NF / 4];     // 51.2 MB fp32 hidden
__device__ int g_deg[N_NODES];
__device__ int g_off[N_NODES];
__device__ int g_cur[N_NODES];
__device__ int g_srcs[E_MAX];
__device__ int g_bsum[SCAN_NBLK];
__device__ int g_is64;

// ---------------------------------------------------------------------------
// helpers
// ---------------------------------------------------------------------------
__device__ __forceinline__ uint32_t smem_u32(const void* p) {
    uint32_t a;
    asm("{ .reg .u64 t; cvta.to.shared.u64 t, %1; cvt.u32.u64 %0, t; }"
        : "=r"(a) : "l"(p));
    return a;
}

__device__ __forceinline__ uint32_t pack2(__nv_bfloat16 a, __nv_bfloat16 b) {
    __nv_bfloat162 t = __halves2bfloat162(a, b);   // a = low half
    return *reinterpret_cast<uint32_t*>(&t);
}

__device__ __forceinline__ void bf_split(float v, __nv_bfloat16& h, __nv_bfloat16& l) {
    h = __float2bfloat16(v);
    l = __float2bfloat16(v - __bfloat162float(h));
}

// fp32 pair -> bf16 hi-pack + lo-pack
__device__ __forceinline__ void split_pack(float2 v, uint32_t& hp, uint32_t& lp) {
    __nv_bfloat16 h0, l0, h1, l1;
    bf_split(v.x, h0, l0);
    bf_split(v.y, h1, l1);
    hp = pack2(h0, h1);
    lp = pack2(l0, l1);
}

__device__ __forceinline__ void mma16816(float* d, const uint32_t* a,
                                         uint32_t b0, uint32_t b1) {
    asm volatile(
        "mma.sync.aligned.m16n8k16.row.col.f32.bf16.bf16.f32 "
        "{%0,%1,%2,%3}, {%4,%5,%6,%7}, {%8,%9}, {%0,%1,%2,%3};"
        : "+f"(d[0]), "+f"(d[1]), "+f"(d[2]), "+f"(d[3])
        : "r"(a[0]), "r"(a[1]), "r"(a[2]), "r"(a[3]), "r"(b0), "r"(b1));
}

__device__ __forceinline__ void ldsm_x4_trans(uint32_t* r, uint32_t addr) {
    asm volatile(
        "ldmatrix.sync.aligned.m8n8.x4.trans.shared.b16 {%0,%1,%2,%3}, [%4];"
        : "=r"(r[0]), "=r"(r[1]), "=r"(r[2]), "=r"(r[3]) : "r"(addr));
}

// ===========================================================================
// Preprocessing
// ===========================================================================
__global__ void init_kernel(const int* __restrict__ ei_words) {
    int i = blockIdx.x * blockDim.x + threadIdx.x;
    if (i < N_NODES) g_deg[i] = 0;
    if (i == 0) {
        int is64 = 1;
        #pragma unroll
        for (int k = 0; k < 64; k++)
            if (ei_words[2 * k + 1] != 0) { is64 = 0; break; }
        g_is64 = is64;
    }
}

__device__ __forceinline__ int load_edge(const void* ei, long long idx) {
    return g_is64 ? (int)((const long long*)ei)[idx] : ((const int*)ei)[idx];
}

__global__ void hist_kernel(const void* __restrict__ ei, int E) {
    int e = blockIdx.x * blockDim.x + threadIdx.x;
    if (e >= E) return;
    int d = load_edge(ei, (long long)E + e);
    d = min(max(d, 0), N_NODES - 1);
    atomicAdd(&g_deg[d], 1);
}

__global__ void scan1_kernel() {
    __shared__ int warp_sums[32];
    int tid = threadIdx.x, lane = tid & 31, wid = tid >> 5;
    int i = blockIdx.x * SCAN_BLK + tid;
    int v = (i < N_NODES) ? g_deg[i] : 0;
    int s = v;
    #pragma unroll
    for (int d = 1; d < 32; d <<= 1) {
        int t = __shfl_up_sync(0xFFFFFFFFu, s, d);
        if (lane >= d) s += t;
    }
    if (lane == 31) warp_sums[wid] = s;
    __syncthreads();
    if (wid == 0) {
        int ws = warp_sums[lane];
        #pragma unroll
        for (int d = 1; d < 32; d <<= 1) {
            int t = __shfl_up_sync(0xFFFFFFFFu, ws, d);
            if (lane >= d) ws += t;
        }
        warp_sums[lane] = ws;
    }
    __syncthreads();
    int warp_off = (wid == 0) ? 0 : warp_sums[wid - 1];
    if (i < N_NODES) g_off[i] = warp_off + s - v;
    if (tid == SCAN_BLK - 1) g_bsum[blockIdx.x] = warp_off + s;
}

// scan2+scan3 merged: each block redundantly computes its own prefix of the
// 98 block sums in smem, then finalizes offsets + cursors for its chunk.
__global__ void scan23_kernel() {
    __shared__ int sh[SCAN_NBLK];
    __shared__ int myoff_s;
    int tid = threadIdx.x;
    if (tid < SCAN_NBLK) sh[tid] = g_bsum[tid];
    __syncthreads();
    if (tid == 0) {
        int run = 0;
        int me = blockIdx.x;
        for (int k = 0; k < SCAN_NBLK; k++) {
            if (k == me) break;
            run += sh[k];
        }
        myoff_s = run;
    }
    __syncthreads();
    int i = blockIdx.x * SCAN_BLK + tid;
    if (i < N_NODES) {
        int o = g_off[i] + myoff_s;
        g_off[i] = o;
        g_cur[i] = o;
    }
}

__global__ void fill_kernel(const void* __restrict__ ei, int E) {
    int e = blockIdx.x * blockDim.x + threadIdx.x;
    if (e >= E) return;
    int s = load_edge(ei, e);
    int d = load_edge(ei, (long long)E + e);
    s = min(max(s, 0), N_NODES - 1);
    d = min(max(d, 0), N_NODES - 1);
    int pos = atomicAdd(&g_cur[d], 1);
    if (pos >= 0 && pos < E_MAX) g_srcs[pos] = s;
}

// ---------------------------------------------------------------------------
// Gather-aggregate: one warp per node, fp32 in/out (L2-throughput bound,
// near the ~74us floor). use_h: gather from g_h4 (layer 2).
// ---------------------------------------------------------------------------
__global__ __launch_bounds__(512) void aggregate_kernel(
    const float* __restrict__ feat, int use_h)
{
    const float4* f = use_h ? g_h4 : reinterpret_cast<const float4*>(feat);
    int w = (blockIdx.x * blockDim.x + threadIdx.x) >> 5;
    int lane = threadIdx.x & 31;
    if (w >= N_NODES) return;
    int off = g_off[w], deg = g_deg[w];
    float4 a0 = make_float4(0.f, 0.f, 0.f, 0.f);
    float4 a1 = make_float4(0.f, 0.f, 0.f, 0.f);
    for (int j0 = 0; j0 < deg; j0 += 32) {
        int nj = min(32, deg - j0);
        int my = (lane < nj) ? g_srcs[off + j0 + lane] : 0;
        int t = 0;
        for (; t + 2 <= nj; t += 2) {
            int s0 = __shfl_sync(0xFFFFFFFFu, my, t);
            int s1 = __shfl_sync(0xFFFFFFFFu, my, t + 1);
            float4 v0 = f[(size_t)s0 * 32 + lane];
            float4 v1 = f[(size_t)s1 * 32 + lane];
            a0.x += v0.x; a0.y += v0.y; a0.z += v0.z; a0.w += v0.w;
            a1.x += v1.x; a1.y += v1.y; a1.z += v1.z; a1.w += v1.w;
        }
        if (t < nj) {
            int s0 = __shfl_sync(0xFFFFFFFFu, my, t);
            float4 v0 = f[(size_t)s0 * 32 + lane];
            a0.x += v0.x; a0.y += v0.y; a0.z += v0.z; a0.w += v0.w;
        }
    }
    float iv = (deg > 0) ? 1.0f / (float)deg : 0.0f;
    float4 r;
    r.x = (a0.x + a1.x) * iv; r.y = (a0.y + a1.y) * iv;
    r.z = (a0.z + a1.z) * iv; r.w = (a0.w + a1.w) * iv;
    g_agg4[(size_t)w * 32 + lane] = r;
}

// ===========================================================================
// HMMA fused linear: C[N x 128] = [agg | x_or_h] (K=256, fp32) @ B + bias
// B = [Wl;Wr]^T bf16 hi/lo in smem (stride 136, conflict-free ldmatrix).
// A read fp32, split to bf16 hi/lo in registers per k-step.
// 3 products AhBh + AhBl + AlBh, fp32 accum.
// NEW vs R14: (a) A loads for k-step ks+1 prefetched into registers before
// the MMA block of ks (hides L2 latency at unroll 1 without spill);
// (b) bias cached in registers once per CTA (was 32 LDG per tile).
// k-loop stays "#pragma unroll 1" (full unroll spilled -> guard violation).
// ===========================================================================
template <bool RELU>
__global__ __launch_bounds__(256, 1) void mma_gemm_kernel(
    const float* __restrict__ Xin,
    const float* __restrict__ Wl, const float* __restrict__ Wr,
    const float* __restrict__ bias, float* __restrict__ outf, int N,
    int use_h_in)
{
    const float* aggp = reinterpret_cast<const float*>(g_agg4);
    const float* xp = use_h_in ? reinterpret_cast<const float*>(g_h4) : Xin;
    float* op = RELU ? reinterpret_cast<float*>(g_h4) : outf;

    extern __shared__ __nv_bfloat16 smem[];
    __nv_bfloat16* b_hi = smem;                 // [256][136]
    __nv_bfloat16* b_lo = smem + 256 * 136;

    int tid = threadIdx.x;
    // Stage B = [Wl;Wr]^T : B[k][n] = (k<128 ? Wl[n][k] : Wr[n][k-128])
    for (int i = tid; i < 256 * 128; i += 256) {
        int k = i >> 7, n = i & 127;
        float wv = (k < 128) ? Wl[n * 128 + k] : Wr[n * 128 + (k - 128)];
        __nv_bfloat16 hb, lb;
        bf_split(wv, hb, lb);
        b_hi[k * 136 + n] = hb;
        b_lo[k * 136 + n] = lb;
    }
    __syncthreads();

    uint32_t sb_hi = smem_u32(b_hi), sb_lo = smem_u32(b_lo);
    int warp = tid >> 5, lane = tid & 31;
    int qp = lane & 3, qr = lane >> 2;           // col-pair / row-in-8
    int lm_k = (lane & 15);
    int lm_n8 = (lane >> 4) << 3;

    // Bias cached in registers (per-lane: cols nt*8 + qp*2, +1)
    float bc0[16], bc1[16];
    #pragma unroll
    for (int nt = 0; nt < 16; nt++) {
        int n = nt * 8 + qp * 2;
        bc0[nt] = __ldg(bias + n);
        bc1[nt] = __ldg(bias + n + 1);
    }

    int ntiles = (N + 15) >> 4;
    for (int tile = blockIdx.x * 8 + warp; tile < ntiles; tile += gridDim.x * 8) {
        int row0 = tile << 4;
        int rA0 = row0 + qr;
        int rA1 = rA0 + 8;
        if (rA1 >= N) rA1 = N - 1;
        if (rA0 >= N) rA0 = N - 1;

        float d[16][4];
        #pragma unroll
        for (int nt = 0; nt < 16; nt++) {
            d[nt][0] = bc0[nt]; d[nt][1] = bc1[nt];
            d[nt][2] = bc0[nt]; d[nt][3] = bc1[nt];
        }

        // A-load helper (k-step ks -> 4 float2 values)
        auto loadA = [&](int ks, float2* v) {
            int kb = ks * 16;
            const float* srcA = (kb < 128) ? aggp : xp;
            int c0 = ((kb < 128) ? kb : kb - 128) + qp * 2;
            const float* r0p = srcA + (size_t)rA0 * NF + c0;
            const float* r1p = srcA + (size_t)rA1 * NF + c0;
            v[0] = *reinterpret_cast<const float2*>(r0p);
            v[1] = *reinterpret_cast<const float2*>(r1p);
            v[2] = *reinterpret_cast<const float2*>(r0p + 8);
            v[3] = *reinterpret_cast<const float2*>(r1p + 8);
        };

        float2 va[4], vb[4];
        loadA(0, va);

        #pragma unroll 1
        for (int ks = 0; ks < 16; ks++) {
            if (ks < 15) loadA(ks + 1, vb);     // prefetch next k-step

            uint32_t ah[4], al[4];
            split_pack(va[0], ah[0], al[0]);
            split_pack(va[1], ah[1], al[1]);
            split_pack(va[2], ah[2], al[2]);
            split_pack(va[3], ah[3], al[3]);

            uint32_t rowoff = (uint32_t)(((ks << 4) + lm_k) * 136) * 2u;
            #pragma unroll
            for (int ng = 0; ng < 8; ng++) {
                uint32_t coloff = (uint32_t)(ng * 16 + lm_n8) * 2u;
                uint32_t bh[4], bl[4];
                ldsm_x4_trans(bh, sb_hi + rowoff + coloff);
                ldsm_x4_trans(bl, sb_lo + rowoff + coloff);
                mma16816(d[ng * 2],     ah, bh[0], bh[1]);
                mma16816(d[ng * 2],     ah, bl[0], bl[1]);
                mma16816(d[ng * 2],     al, bh[0], bh[1]);
                mma16816(d[ng * 2 + 1], ah, bh[2], bh[3]);
                mma16816(d[ng * 2 + 1], ah, bl[2], bl[3]);
                mma16816(d[ng * 2 + 1], al, bh[2], bh[3]);
            }
            va[0] = vb[0]; va[1] = vb[1]; va[2] = vb[2]; va[3] = vb[3];
        }

        // Epilogue: fp32 (h buffer for layer 1, final out for layer 2).
        int ra = row0 + qr, rb = ra + 8;
        #pragma unroll
        for (int nt = 0; nt < 16; nt++) {
            int n = nt * 8 + qp * 2;
            float v0 = d[nt][0], v1 = d[nt][1], v2 = d[nt][2], v3 = d[nt][3];
            if (RELU) {
                v0 = fmaxf(v0, 0.f); v1 = fmaxf(v1, 0.f);
                v2 = fmaxf(v2, 0.f); v3 = fmaxf(v3, 0.f);
            }
            if (ra < N)
                *reinterpret_cast<float2*>(op + (size_t)ra * NF + n) = make_float2(v0, v1);
            if (rb < N)
                *reinterpret_cast<float2*>(op + (size_t)rb * NF + n) = make_float2(v2, v3);
        }
    }
}

// ---------------------------------------------------------------------------
// init -> hist -> scan1 -> scan23 -> fill -> agg1 -> gemm1 -> agg2 -> gemm2
// ---------------------------------------------------------------------------
extern "C" void kernel_launch(void* const* d_in, const int* in_sizes, int n_in,
                              void* d_out, int out_size) {
    const float* x = nullptr;
    const void* ei = nullptr;
    const float* w[4] = {nullptr, nullptr, nullptr, nullptr};
    const float* b[2] = {nullptr, nullptr};
    int nw = 0, nb = 0, E = 0, N = N_NODES;

    for (int i = 0; i < n_in; i++) {
        int sz = in_sizes[i];
        if (sz == N_NODES * NF) {
            x = (const float*)d_in[i];
        } else if (sz == NF * NF) {
            if (nw < 4) w[nw++] = (const float*)d_in[i];
        } else if (sz == NF) {
            if (nb < 2) b[nb++] = (const float*)d_in[i];
        } else {
            ei = d_in[i];
            E = sz / 2;
        }
    }
    if (E > E_MAX) E = E_MAX;
    const float *w1l = w[0], *w1r = w[1], *w2l = w[2], *w2r = w[3];
    const float *b1 = b[0], *b2 = b[1];
    float* out = (float*)d_out;

    size_t gemm_smem = (size_t)2 * 256 * 136 * sizeof(__nv_bfloat16);  // 136 KB
    cudaFuncSetAttribute(mma_gemm_kernel<true>,  cudaFuncAttributeMaxDynamicSharedMemorySize, (int)gemm_smem);
    cudaFuncSetAttribute(mma_gemm_kernel<false>, cudaFuncAttributeMaxDynamicSharedMemorySize, (int)gemm_smem);

    int agg_grid = (N_NODES * 32 + 511) / 512;

    init_kernel<<<(N_NODES + 511) / 512, 512>>>((const int*)ei);
    if (E > 0) hist_kernel<<<(E + 511) / 512, 512>>>(ei, E);
    scan1_kernel<<<SCAN_NBLK, SCAN_BLK>>>();
    scan23_kernel<<<SCAN_NBLK, SCAN_BLK>>>();
    if (E > 0) fill_kernel<<<(E + 511) / 512, 512>>>(ei, E);

    // Layer 1: [agg(x) | x] -> h (fp32, g_h4)
    aggregate_kernel<<<agg_grid, 512>>>(x, 0);
    mma_gemm_kernel<true><<<296, 256, gemm_smem>>>(x, w1l, w1r, b1, out, N, 0);

    // Layer 2: [agg(h) | h] -> out
    aggregate_kernel<<<agg_grid, 512>>>(x, 1);
    mma_gemm_kernel<false><<<296, 256, gemm_smem>>>(x, w2l, w2r, b2, out, N, 1);
}

// round 16
// speedup vs baseline: 1.5257x; 1.0004x over previous
#include <cuda_runtime.h>
#include <cuda_bf16.h>
#include <cstdint>

#define NF 128
#define N_NODES 100000
#define E_MAX 2000000
#define SCAN_BLK 1024
#define SCAN_NBLK ((N_NODES + SCAN_BLK - 1) / SCAN_BLK)   // 98

// Scratch: static device globals, ~112MB total (proven safe footprint;
// >=214MB of globals trips the harness alloc-guard arena).
__device__ float4 g_agg4[(size_t)N_NODES * NF / 4];   // 51.2 MB fp32 mean rows
__device__ float4 g_h4[(size_t)N_NODES * NF / 4];     // 51.2 MB fp32 hidden
__device__ int g_deg[N_NODES];
__device__ int g_off[N_NODES];
__device__ int g_cur[N_NODES];
__device__ int g_srcs[E_MAX];
__device__ int g_bsum[SCAN_NBLK];
__device__ int g_is64;

// ---------------------------------------------------------------------------
// helpers
// ---------------------------------------------------------------------------
__device__ __forceinline__ uint32_t smem_u32(const void* p) {
    uint32_t a;
    asm("{ .reg .u64 t; cvta.to.shared.u64 t, %1; cvt.u32.u64 %0, t; }"
        : "=r"(a) : "l"(p));
    return a;
}

__device__ __forceinline__ uint32_t pack2(__nv_bfloat16 a, __nv_bfloat16 b) {
    __nv_bfloat162 t = __halves2bfloat162(a, b);   // a = low half
    return *reinterpret_cast<uint32_t*>(&t);
}

__device__ __forceinline__ void bf_split(float v, __nv_bfloat16& h, __nv_bfloat16& l) {
    h = __float2bfloat16(v);
    l = __float2bfloat16(v - __bfloat162float(h));
}

// fp32 pair -> bf16 hi-pack + lo-pack
__device__ __forceinline__ void split_pack(float2 v, uint32_t& hp, uint32_t& lp) {
    __nv_bfloat16 h0, l0, h1, l1;
    bf_split(v.x, h0, l0);
    bf_split(v.y, h1, l1);
    hp = pack2(h0, h1);
    lp = pack2(l0, l1);
}

__device__ __forceinline__ void mma16816(float* d, const uint32_t* a,
                                         uint32_t b0, uint32_t b1) {
    asm volatile(
        "mma.sync.aligned.m16n8k16.row.col.f32.bf16.bf16.f32 "
        "{%0,%1,%2,%3}, {%4,%5,%6,%7}, {%8,%9}, {%0,%1,%2,%3};"
        : "+f"(d[0]), "+f"(d[1]), "+f"(d[2]), "+f"(d[3])
        : "r"(a[0]), "r"(a[1]), "r"(a[2]), "r"(a[3]), "r"(b0), "r"(b1));
}

__device__ __forceinline__ void ldsm_x4_trans(uint32_t* r, uint32_t addr) {
    asm volatile(
        "ldmatrix.sync.aligned.m8n8.x4.trans.shared.b16 {%0,%1,%2,%3}, [%4];"
        : "=r"(r[0]), "=r"(r[1]), "=r"(r[2]), "=r"(r[3]) : "r"(addr));
}

// ===========================================================================
// Preprocessing
// ===========================================================================
__global__ void init_kernel(const int* __restrict__ ei_words) {
    int i = blockIdx.x * blockDim.x + threadIdx.x;
    if (i < N_NODES) g_deg[i] = 0;
    if (i == 0) {
        int is64 = 1;
        #pragma unroll
        for (int k = 0; k < 64; k++)
            if (ei_words[2 * k + 1] != 0) { is64 = 0; break; }
        g_is64 = is64;
    }
}

__device__ __forceinline__ int load_edge(const void* ei, long long idx) {
    return g_is64 ? (int)((const long long*)ei)[idx] : ((const int*)ei)[idx];
}

__global__ void hist_kernel(const void* __restrict__ ei, int E) {
    int e = blockIdx.x * blockDim.x + threadIdx.x;
    if (e >= E) return;
    int d = load_edge(ei, (long long)E + e);
    d = min(max(d, 0), N_NODES - 1);
    atomicAdd(&g_deg[d], 1);
}

__global__ void scan1_kernel() {
    __shared__ int warp_sums[32];
    int tid = threadIdx.x, lane = tid & 31, wid = tid >> 5;
    int i = blockIdx.x * SCAN_BLK + tid;
    int v = (i < N_NODES) ? g_deg[i] : 0;
    int s = v;
    #pragma unroll
    for (int d = 1; d < 32; d <<= 1) {
        int t = __shfl_up_sync(0xFFFFFFFFu, s, d);
        if (lane >= d) s += t;
    }
    if (lane == 31) warp_sums[wid] = s;
    __syncthreads();
    if (wid == 0) {
        int ws = warp_sums[lane];
        #pragma unroll
        for (int d = 1; d < 32; d <<= 1) {
            int t = __shfl_up_sync(0xFFFFFFFFu, ws, d);
            if (lane >= d) ws += t;
        }
        warp_sums[lane] = ws;
    }
    __syncthreads();
    int warp_off = (wid == 0) ? 0 : warp_sums[wid - 1];
    if (i < N_NODES) g_off[i] = warp_off + s - v;
    if (tid == SCAN_BLK - 1) g_bsum[blockIdx.x] = warp_off + s;
}

// scan2+scan3 merged: each block redundantly computes its own prefix of the
// 98 block sums in smem, then finalizes offsets + cursors for its chunk.
__global__ void scan23_kernel() {
    __shared__ int sh[SCAN_NBLK];
    __shared__ int myoff_s;
    int tid = threadIdx.x;
    if (tid < SCAN_NBLK) sh[tid] = g_bsum[tid];
    __syncthreads();
    if (tid == 0) {
        int run = 0;
        int me = blockIdx.x;
        for (int k = 0; k < SCAN_NBLK; k++) {
            if (k == me) break;
            run += sh[k];
        }
        myoff_s = run;
    }
    __syncthreads();
    int i = blockIdx.x * SCAN_BLK + tid;
    if (i < N_NODES) {
        int o = g_off[i] + myoff_s;
        g_off[i] = o;
        g_cur[i] = o;
    }
}

__global__ void fill_kernel(const void* __restrict__ ei, int E) {
    int e = blockIdx.x * blockDim.x + threadIdx.x;
    if (e >= E) return;
    int s = load_edge(ei, e);
    int d = load_edge(ei, (long long)E + e);
    s = min(max(s, 0), N_NODES - 1);
    d = min(max(d, 0), N_NODES - 1);
    int pos = atomicAdd(&g_cur[d], 1);
    if (pos >= 0 && pos < E_MAX) g_srcs[pos] = s;
}

// ---------------------------------------------------------------------------
// Gather-aggregate: one warp per node, fp32 in/out (L2-throughput bound,
// near the ~74us floor). use_h: gather from g_h4 (layer 2).
// ---------------------------------------------------------------------------
__global__ __launch_bounds__(512) void aggregate_kernel(
    const float* __restrict__ feat, int use_h)
{
    const float4* f = use_h ? g_h4 : reinterpret_cast<const float4*>(feat);
    int w = (blockIdx.x * blockDim.x + threadIdx.x) >> 5;
    int lane = threadIdx.x & 31;
    if (w >= N_NODES) return;
    int off = g_off[w], deg = g_deg[w];
    float4 a0 = make_float4(0.f, 0.f, 0.f, 0.f);
    float4 a1 = make_float4(0.f, 0.f, 0.f, 0.f);
    for (int j0 = 0; j0 < deg; j0 += 32) {
        int nj = min(32, deg - j0);
        int my = (lane < nj) ? g_srcs[off + j0 + lane] : 0;
        int t = 0;
        for (; t + 2 <= nj; t += 2) {
            int s0 = __shfl_sync(0xFFFFFFFFu, my, t);
            int s1 = __shfl_sync(0xFFFFFFFFu, my, t + 1);
            float4 v0 = f[(size_t)s0 * 32 + lane];
            float4 v1 = f[(size_t)s1 * 32 + lane];
            a0.x += v0.x; a0.y += v0.y; a0.z += v0.z; a0.w += v0.w;
            a1.x += v1.x; a1.y += v1.y; a1.z += v1.z; a1.w += v1.w;
        }
        if (t < nj) {
            int s0 = __shfl_sync(0xFFFFFFFFu, my, t);
            float4 v0 = f[(size_t)s0 * 32 + lane];
            a0.x += v0.x; a0.y += v0.y; a0.z += v0.z; a0.w += v0.w;
        }
    }
    float iv = (deg > 0) ? 1.0f / (float)deg : 0.0f;
    float4 r;
    r.x = (a0.x + a1.x) * iv; r.y = (a0.y + a1.y) * iv;
    r.z = (a0.z + a1.z) * iv; r.w = (a0.w + a1.w) * iv;
    g_agg4[(size_t)w * 32 + lane] = r;
}

// ===========================================================================
// HMMA fused linear: C[N x 128] = [agg | x_or_h] (K=256, fp32) @ B + bias
// B = [Wl;Wr]^T bf16 hi/lo in smem (stride 136, conflict-free ldmatrix).
// A read fp32, split to bf16 hi/lo in registers per k-step.
// 3 products AhBh + AhBl + AlBh, fp32 accum.
// NEW vs R14: (a) A loads for k-step ks+1 prefetched into registers before
// the MMA block of ks (hides L2 latency at unroll 1 without spill);
// (b) bias cached in registers once per CTA (was 32 LDG per tile).
// k-loop stays "#pragma unroll 1" (full unroll spilled -> guard violation).
// ===========================================================================
template <bool RELU>
__global__ __launch_bounds__(256, 1) void mma_gemm_kernel(
    const float* __restrict__ Xin,
    const float* __restrict__ Wl, const float* __restrict__ Wr,
    const float* __restrict__ bias, float* __restrict__ outf, int N,
    int use_h_in)
{
    const float* aggp = reinterpret_cast<const float*>(g_agg4);
    const float* xp = use_h_in ? reinterpret_cast<const float*>(g_h4) : Xin;
    float* op = RELU ? reinterpret_cast<float*>(g_h4) : outf;

    extern __shared__ __nv_bfloat16 smem[];
    __nv_bfloat16* b_hi = smem;                 // [256][136]
    __nv_bfloat16* b_lo = smem + 256 * 136;

    int tid = threadIdx.x;
    // Stage B = [Wl;Wr]^T : B[k][n] = (k<128 ? Wl[n][k] : Wr[n][k-128])
    for (int i = tid; i < 256 * 128; i += 256) {
        int k = i >> 7, n = i & 127;
        float wv = (k < 128) ? Wl[n * 128 + k] : Wr[n * 128 + (k - 128)];
        __nv_bfloat16 hb, lb;
        bf_split(wv, hb, lb);
        b_hi[k * 136 + n] = hb;
        b_lo[k * 136 + n] = lb;
    }
    __syncthreads();

    uint32_t sb_hi = smem_u32(b_hi), sb_lo = smem_u32(b_lo);
    int warp = tid >> 5, lane = tid & 31;
    int qp = lane & 3, qr = lane >> 2;           // col-pair / row-in-8
    int lm_k = (lane & 15);
    int lm_n8 = (lane >> 4) << 3;

    // Bias cached in registers (per-lane: cols nt*8 + qp*2, +1)
    float bc0[16], bc1[16];
    #pragma unroll
    for (int nt = 0; nt < 16; nt++) {
        int n = nt * 8 + qp * 2;
        bc0[nt] = __ldg(bias + n);
        bc1[nt] = __ldg(bias + n + 1);
    }

    int ntiles = (N + 15) >> 4;
    for (int tile = blockIdx.x * 8 + warp; tile < ntiles; tile += gridDim.x * 8) {
        int row0 = tile << 4;
        int rA0 = row0 + qr;
        int rA1 = rA0 + 8;
        if (rA1 >= N) rA1 = N - 1;
        if (rA0 >= N) rA0 = N - 1;

        float d[16][4];
        #pragma unroll
        for (int nt = 0; nt < 16; nt++) {
            d[nt][0] = bc0[nt]; d[nt][1] = bc1[nt];
            d[nt][2] = bc0[nt]; d[nt][3] = bc1[nt];
        }

        // A-load helper (k-step ks -> 4 float2 values)
        auto loadA = [&](int ks, float2* v) {
            int kb = ks * 16;
            const float* srcA = (kb < 128) ? aggp : xp;
            int c0 = ((kb < 128) ? kb : kb - 128) + qp * 2;
            const float* r0p = srcA + (size_t)rA0 * NF + c0;
            const float* r1p = srcA + (size_t)rA1 * NF + c0;
            v[0] = *reinterpret_cast<const float2*>(r0p);
            v[1] = *reinterpret_cast<const float2*>(r1p);
            v[2] = *reinterpret_cast<const float2*>(r0p + 8);
            v[3] = *reinterpret_cast<const float2*>(r1p + 8);
        };

        float2 va[4], vb[4];
        loadA(0, va);

        #pragma unroll 1
        for (int ks = 0; ks < 16; ks++) {
            if (ks < 15) loadA(ks + 1, vb);     // prefetch next k-step

            uint32_t ah[4], al[4];
            split_pack(va[0], ah[0], al[0]);
            split_pack(va[1], ah[1], al[1]);
            split_pack(va[2], ah[2], al[2]);
            split_pack(va[3], ah[3], al[3]);

            uint32_t rowoff = (uint32_t)(((ks << 4) + lm_k) * 136) * 2u;
            #pragma unroll
            for (int ng = 0; ng < 8; ng++) {
                uint32_t coloff = (uint32_t)(ng * 16 + lm_n8) * 2u;
                uint32_t bh[4], bl[4];
                ldsm_x4_trans(bh, sb_hi + rowoff + coloff);
                ldsm_x4_trans(bl, sb_lo + rowoff + coloff);
                mma16816(d[ng * 2],     ah, bh[0], bh[1]);
                mma16816(d[ng * 2],     ah, bl[0], bl[1]);
                mma16816(d[ng * 2],     al, bh[0], bh[1]);
                mma16816(d[ng * 2 + 1], ah, bh[2], bh[3]);
                mma16816(d[ng * 2 + 1], ah, bl[2], bl[3]);
                mma16816(d[ng * 2 + 1], al, bh[2], bh[3]);
            }
            va[0] = vb[0]; va[1] = vb[1]; va[2] = vb[2]; va[3] = vb[3];
        }

        // Epilogue: fp32 (h buffer for layer 1, final out for layer 2).
        int ra = row0 + qr, rb = ra + 8;
        #pragma unroll
        for (int nt = 0; nt < 16; nt++) {
            int n = nt * 8 + qp * 2;
            float v0 = d[nt][0], v1 = d[nt][1], v2 = d[nt][2], v3 = d[nt][3];
            if (RELU) {
                v0 = fmaxf(v0, 0.f); v1 = fmaxf(v1, 0.f);
                v2 = fmaxf(v2, 0.f); v3 = fmaxf(v3, 0.f);
            }
            if (ra < N)
                *reinterpret_cast<float2*>(op + (size_t)ra * NF + n) = make_float2(v0, v1);
            if (rb < N)
                *reinterpret_cast<float2*>(op + (size_t)rb * NF + n) = make_float2(v2, v3);
        }
    }
}

// ---------------------------------------------------------------------------
// init -> hist -> scan1 -> scan23 -> fill -> agg1 -> gemm1 -> agg2 -> gemm2
// ---------------------------------------------------------------------------
extern "C" void kernel_launch(void* const* d_in, const int* in_sizes, int n_in,
                              void* d_out, int out_size) {
    const float* x = nullptr;
    const void* ei = nullptr;
    const float* w[4] = {nullptr, nullptr, nullptr, nullptr};
    const float* b[2] = {nullptr, nullptr};
    int nw = 0, nb = 0, E = 0, N = N_NODES;

    for (int i = 0; i < n_in; i++) {
        int sz = in_sizes[i];
        if (sz == N_NODES * NF) {
            x = (const float*)d_in[i];
        } else if (sz == NF * NF) {
            if (nw < 4) w[nw++] = (const float*)d_in[i];
        } else if (sz == NF) {
            if (nb < 2) b[nb++] = (const float*)d_in[i];
        } else {
            ei = d_in[i];
            E = sz / 2;
        }
    }
    if (E > E_MAX) E = E_MAX;
    const float *w1l = w[0], *w1r = w[1], *w2l = w[2], *w2r = w[3];
    const float *b1 = b[0], *b2 = b[1];
    float* out = (float*)d_out;

    size_t gemm_smem = (size_t)2 * 256 * 136 * sizeof(__nv_bfloat16);  // 136 KB
    cudaFuncSetAttribute(mma_gemm_kernel<true>,  cudaFuncAttributeMaxDynamicSharedMemorySize, (int)gemm_smem);
    cudaFuncSetAttribute(mma_gemm_kernel<false>, cudaFuncAttributeMaxDynamicSharedMemorySize, (int)gemm_smem);

    int agg_grid = (N_NODES * 32 + 511) / 512;

    init_kernel<<<(N_NODES + 511) / 512, 512>>>((const int*)ei);
    if (E > 0) hist_kernel<<<(E + 511) / 512, 512>>>(ei, E);
    scan1_kernel<<<SCAN_NBLK, SCAN_BLK>>>();
    scan23_kernel<<<SCAN_NBLK, SCAN_BLK>>>();
    if (E > 0) fill_kernel<<<(E + 511) / 512, 512>>>(ei, E);

    // Layer 1: [agg(x) | x] -> h (fp32, g_h4)
    aggregate_kernel<<<agg_grid, 512>>>(x, 0);
    mma_gemm_kernel<true><<<296, 256, gemm_smem>>>(x, w1l, w1r, b1, out, N, 0);

    // Layer 2: [agg(h) | h] -> out
    aggregate_kernel<<<agg_grid, 512>>>(x, 1);
    mma_gemm_kernel<false><<<296, 256, gemm_smem>>>(x, w2l, w2r, b2, out, N, 1);
}

// round 17
// speedup vs baseline: 1.7016x; 1.1153x over previous
#include <cuda_runtime.h>
#include <cuda_bf16.h>
#include <cstdint>

#define NF 128
#define N_NODES 100000
#define E_MAX 2000000
#define SCAN_BLK 1024
#define SCAN_NBLK ((N_NODES + SCAN_BLK - 1) / SCAN_BLK)   // 98

// Scratch: static device globals, ~112MB total (proven safe footprint).
__device__ float4 g_agg4[(size_t)N_NODES * NF / 4];   // 51.2 MB fp32 mean rows
__device__ float4 g_h4[(size_t)N_NODES * NF / 4];     // 51.2 MB fp32 hidden
__device__ int g_deg[N_NODES];
__device__ int g_off[N_NODES];
__device__ int g_cur[N_NODES];
__device__ int g_srcs[E_MAX];
__device__ int g_bsum[SCAN_NBLK];
__device__ int g_is64;

// ---------------------------------------------------------------------------
// helpers
// ---------------------------------------------------------------------------
__device__ __forceinline__ uint32_t smem_u32(const void* p) {
    uint32_t a;
    asm("{ .reg .u64 t; cvta.to.shared.u64 t, %1; cvt.u32.u64 %0, t; }"
        : "=r"(a) : "l"(p));
    return a;
}

__device__ __forceinline__ uint32_t pack2(__nv_bfloat16 a, __nv_bfloat16 b) {
    __nv_bfloat162 t = __halves2bfloat162(a, b);   // a = low half
    return *reinterpret_cast<uint32_t*>(&t);
}

__device__ __forceinline__ void bf_split(float v, __nv_bfloat16& h, __nv_bfloat16& l) {
    h = __float2bfloat16(v);
    l = __float2bfloat16(v - __bfloat162float(h));
}

__device__ __forceinline__ void split_pack(float2 v, uint32_t& hp, uint32_t& lp) {
    __nv_bfloat16 h0, l0, h1, l1;
    bf_split(v.x, h0, l0);
    bf_split(v.y, h1, l1);
    hp = pack2(h0, h1);
    lp = pack2(l0, l1);
}

__device__ __forceinline__ void mma16816(float* d, const uint32_t* a,
                                         uint32_t b0, uint32_t b1) {
    asm volatile(
        "mma.sync.aligned.m16n8k16.row.col.f32.bf16.bf16.f32 "
        "{%0,%1,%2,%3}, {%4,%5,%6,%7}, {%8,%9}, {%0,%1,%2,%3};"
        : "+f"(d[0]), "+f"(d[1]), "+f"(d[2]), "+f"(d[3])
        : "r"(a[0]), "r"(a[1]), "r"(a[2]), "r"(a[3]), "r"(b0), "r"(b1));
}

__device__ __forceinline__ void ldsm_x4_trans(uint32_t* r, uint32_t addr) {
    asm volatile(
        "ldmatrix.sync.aligned.m8n8.x4.trans.shared.b16 {%0,%1,%2,%3}, [%4];"
        : "=r"(r[0]), "=r"(r[1]), "=r"(r[2]), "=r"(r[3]) : "r"(addr));
}

// ===========================================================================
// Preprocessing
// ===========================================================================
__global__ void init_kernel(const int* __restrict__ ei_words) {
    int i = blockIdx.x * blockDim.x + threadIdx.x;
    if (i < N_NODES) g_deg[i] = 0;
    if (i == 0) {
        int is64 = 1;
        #pragma unroll
        for (int k = 0; k < 64; k++)
            if (ei_words[2 * k + 1] != 0) { is64 = 0; break; }
        g_is64 = is64;
    }
}

__device__ __forceinline__ int load_edge(const void* ei, long long idx) {
    return g_is64 ? (int)((const long long*)ei)[idx] : ((const int*)ei)[idx];
}

__global__ void hist_kernel(const void* __restrict__ ei, int E) {
    int e = blockIdx.x * blockDim.x + threadIdx.x;
    if (e >= E) return;
    int d = load_edge(ei, (long long)E + e);
    d = min(max(d, 0), N_NODES - 1);
    atomicAdd(&g_deg[d], 1);
}

__global__ void scan1_kernel() {
    __shared__ int warp_sums[32];
    int tid = threadIdx.x, lane = tid & 31, wid = tid >> 5;
    int i = blockIdx.x * SCAN_BLK + tid;
    int v = (i < N_NODES) ? g_deg[i] : 0;
    int s = v;
    #pragma unroll
    for (int d = 1; d < 32; d <<= 1) {
        int t = __shfl_up_sync(0xFFFFFFFFu, s, d);
        if (lane >= d) s += t;
    }
    if (lane == 31) warp_sums[wid] = s;
    __syncthreads();
    if (wid == 0) {
        int ws = warp_sums[lane];
        #pragma unroll
        for (int d = 1; d < 32; d <<= 1) {
            int t = __shfl_up_sync(0xFFFFFFFFu, ws, d);
            if (lane >= d) ws += t;
        }
        warp_sums[lane] = ws;
    }
    __syncthreads();
    int warp_off = (wid == 0) ? 0 : warp_sums[wid - 1];
    if (i < N_NODES) g_off[i] = warp_off + s - v;
    if (tid == SCAN_BLK - 1) g_bsum[blockIdx.x] = warp_off + s;
}

// scan2+scan3 merged: each block computes its own prefix of the 98 block
// sums in smem, then finalizes offsets + cursors for its chunk.
__global__ void scan23_kernel() {
    __shared__ int sh[SCAN_NBLK];
    __shared__ int myoff_s;
    int tid = threadIdx.x;
    if (tid < SCAN_NBLK) sh[tid] = g_bsum[tid];
    __syncthreads();
    if (tid == 0) {
        int run = 0;
        int me = blockIdx.x;
        for (int k = 0; k < SCAN_NBLK; k++) {
            if (k == me) break;
            run += sh[k];
        }
        myoff_s = run;
    }
    __syncthreads();
    int i = blockIdx.x * SCAN_BLK + tid;
    if (i < N_NODES) {
        int o = g_off[i] + myoff_s;
        g_off[i] = o;
        g_cur[i] = o;
    }
}

__global__ void fill_kernel(const void* __restrict__ ei, int E) {
    int e = blockIdx.x * blockDim.x + threadIdx.x;
    if (e >= E) return;
    int s = load_edge(ei, e);
    int d = load_edge(ei, (long long)E + e);
    s = min(max(s, 0), N_NODES - 1);
    d = min(max(d, 0), N_NODES - 1);
    int pos = atomicAdd(&g_cur[d], 1);
    if (pos >= 0 && pos < E_MAX) g_srcs[pos] = s;
}

// ---------------------------------------------------------------------------
// Gather-aggregate: one warp per node, fp32 in/out (L2-throughput bound).
// ---------------------------------------------------------------------------
__global__ __launch_bounds__(512) void aggregate_kernel(
    const float* __restrict__ feat, int use_h)
{
    const float4* f = use_h ? g_h4 : reinterpret_cast<const float4*>(feat);
    int w = (blockIdx.x * blockDim.x + threadIdx.x) >> 5;
    int lane = threadIdx.x & 31;
    if (w >= N_NODES) return;
    int off = g_off[w], deg = g_deg[w];
    float4 a0 = make_float4(0.f, 0.f, 0.f, 0.f);
    float4 a1 = make_float4(0.f, 0.f, 0.f, 0.f);
    for (int j0 = 0; j0 < deg; j0 += 32) {
        int nj = min(32, deg - j0);
        int my = (lane < nj) ? g_srcs[off + j0 + lane] : 0;
        int t = 0;
        for (; t + 2 <= nj; t += 2) {
            int s0 = __shfl_sync(0xFFFFFFFFu, my, t);
            int s1 = __shfl_sync(0xFFFFFFFFu, my, t + 1);
            float4 v0 = f[(size_t)s0 * 32 + lane];
            float4 v1 = f[(size_t)s1 * 32 + lane];
            a0.x += v0.x; a0.y += v0.y; a0.z += v0.z; a0.w += v0.w;
            a1.x += v1.x; a1.y += v1.y; a1.z += v1.z; a1.w += v1.w;
        }
        if (t < nj) {
            int s0 = __shfl_sync(0xFFFFFFFFu, my, t);
            float4 v0 = f[(size_t)s0 * 32 + lane];
            a0.x += v0.x; a0.y += v0.y; a0.z += v0.z; a0.w += v0.w;
        }
    }
    float iv = (deg > 0) ? 1.0f / (float)deg : 0.0f;
    float4 r;
    r.x = (a0.x + a1.x) * iv; r.y = (a0.y + a1.y) * iv;
    r.z = (a0.z + a1.z) * iv; r.w = (a0.w + a1.w) * iv;
    g_agg4[(size_t)w * 32 + lane] = r;
}

// ===========================================================================
// HMMA fused linear: C[N x 128] = [agg | x_or_h] (K=256, fp32) @ B + bias
// NEW vs R16: (a) per k-step the 3 compensation products run as 3 PASSES
// over all 8 n-groups (AhBh, then AhBl, then AlBh) -> same-accumulator MMAs
// are 16 issues apart instead of back-to-back (was RAW-latency bound);
// (b) 384 threads = 12 warps (3/SMSP) for latency hiding; (c) bias in smem
// (frees 32 regs/thread). k-loop stays "#pragma unroll 1" (no spill).
// ===========================================================================
template <bool RELU>
__global__ __launch_bounds__(384, 1) void mma_gemm_kernel(
    const float* __restrict__ Xin,
    const float* __restrict__ Wl, const float* __restrict__ Wr,
    const float* __restrict__ bias, float* __restrict__ outf, int N,
    int use_h_in)
{
    const float* aggp = reinterpret_cast<const float*>(g_agg4);
    const float* xp = use_h_in ? reinterpret_cast<const float*>(g_h4) : Xin;
    float* op = RELU ? reinterpret_cast<float*>(g_h4) : outf;

    extern __shared__ __nv_bfloat16 smem[];
    __nv_bfloat16* b_hi = smem;                       // [256][136]
    __nv_bfloat16* b_lo = smem + 256 * 136;
    float* s_bias = reinterpret_cast<float*>(smem + 2 * 256 * 136);

    int tid = threadIdx.x;
    // Stage B = [Wl;Wr]^T : B[k][n] = (k<128 ? Wl[n][k] : Wr[n][k-128])
    for (int i = tid; i < 256 * 128; i += 384) {
        int k = i >> 7, n = i & 127;
        float wv = (k < 128) ? Wl[n * 128 + k] : Wr[n * 128 + (k - 128)];
        __nv_bfloat16 hb, lb;
        bf_split(wv, hb, lb);
        b_hi[k * 136 + n] = hb;
        b_lo[k * 136 + n] = lb;
    }
    if (tid < 128) s_bias[tid] = bias[tid];
    __syncthreads();

    uint32_t sb_hi = smem_u32(b_hi), sb_lo = smem_u32(b_lo);
    int warp = tid >> 5, lane = tid & 31;
    int qp = lane & 3, qr = lane >> 2;           // col-pair / row-in-8
    int lm_k = (lane & 15);
    int lm_n8 = (lane >> 4) << 3;

    int ntiles = (N + 15) >> 4;
    for (int tile = blockIdx.x * 12 + warp; tile < ntiles; tile += gridDim.x * 12) {
        int row0 = tile << 4;
        int rA0 = row0 + qr;
        int rA1 = rA0 + 8;
        if (rA1 >= N) rA1 = N - 1;
        if (rA0 >= N) rA0 = N - 1;

        float d[16][4];
        #pragma unroll
        for (int nt = 0; nt < 16; nt++) {
            int n = nt * 8 + qp * 2;
            float b0v = s_bias[n], b1v = s_bias[n + 1];
            d[nt][0] = b0v; d[nt][1] = b1v; d[nt][2] = b0v; d[nt][3] = b1v;
        }

        auto loadA = [&](int ks, float2* v) {
            int kb = ks * 16;
            const float* srcA = (kb < 128) ? aggp : xp;
            int c0 = ((kb < 128) ? kb : kb - 128) + qp * 2;
            const float* r0p = srcA + (size_t)rA0 * NF + c0;
            const float* r1p = srcA + (size_t)rA1 * NF + c0;
            v[0] = *reinterpret_cast<const float2*>(r0p);
            v[1] = *reinterpret_cast<const float2*>(r1p);
            v[2] = *reinterpret_cast<const float2*>(r0p + 8);
            v[3] = *reinterpret_cast<const float2*>(r1p + 8);
        };

        float2 va[4], vb[4];
        loadA(0, va);

        #pragma unroll 1
        for (int ks = 0; ks < 16; ks++) {
            if (ks < 15) loadA(ks + 1, vb);     // prefetch next k-step

            uint32_t ah[4], al[4];
            split_pack(va[0], ah[0], al[0]);
            split_pack(va[1], ah[1], al[1]);
            split_pack(va[2], ah[2], al[2]);
            split_pack(va[3], ah[3], al[3]);

            uint32_t rowoff = (uint32_t)(((ks << 4) + lm_k) * 136) * 2u;

            // Pass 1: Ah x Bh  (16 independent MMAs)
            #pragma unroll
            for (int ng = 0; ng < 8; ng++) {
                uint32_t coloff = (uint32_t)(ng * 16 + lm_n8) * 2u;
                uint32_t bh[4];
                ldsm_x4_trans(bh, sb_hi + rowoff + coloff);
                mma16816(d[ng * 2],     ah, bh[0], bh[1]);
                mma16816(d[ng * 2 + 1], ah, bh[2], bh[3]);
            }
            // Pass 2: Ah x Bl
            #pragma unroll
            for (int ng = 0; ng < 8; ng++) {
                uint32_t coloff = (uint32_t)(ng * 16 + lm_n8) * 2u;
                uint32_t bl[4];
                ldsm_x4_trans(bl, sb_lo + rowoff + coloff);
                mma16816(d[ng * 2],     ah, bl[0], bl[1]);
                mma16816(d[ng * 2 + 1], ah, bl[2], bl[3]);
            }
            // Pass 3: Al x Bh
            #pragma unroll
            for (int ng = 0; ng < 8; ng++) {
                uint32_t coloff = (uint32_t)(ng * 16 + lm_n8) * 2u;
                uint32_t bh[4];
                ldsm_x4_trans(bh, sb_hi + rowoff + coloff);
                mma16816(d[ng * 2],     al, bh[0], bh[1]);
                mma16816(d[ng * 2 + 1], al, bh[2], bh[3]);
            }

            va[0] = vb[0]; va[1] = vb[1]; va[2] = vb[2]; va[3] = vb[3];
        }

        // Epilogue: fp32 (h buffer for layer 1, final out for layer 2).
        int ra = row0 + qr, rb = ra + 8;
        #pragma unroll
        for (int nt = 0; nt < 16; nt++) {
            int n = nt * 8 + qp * 2;
            float v0 = d[nt][0], v1 = d[nt][1], v2 = d[nt][2], v3 = d[nt][3];
            if (RELU) {
                v0 = fmaxf(v0, 0.f); v1 = fmaxf(v1, 0.f);
                v2 = fmaxf(v2, 0.f); v3 = fmaxf(v3, 0.f);
            }
            if (ra < N)
                *reinterpret_cast<float2*>(op + (size_t)ra * NF + n) = make_float2(v0, v1);
            if (rb < N)
                *reinterpret_cast<float2*>(op + (size_t)rb * NF + n) = make_float2(v2, v3);
        }
    }
}

// ---------------------------------------------------------------------------
// init -> hist -> scan1 -> scan23 -> fill -> agg1 -> gemm1 -> agg2 -> gemm2
// ---------------------------------------------------------------------------
extern "C" void kernel_launch(void* const* d_in, const int* in_sizes, int n_in,
                              void* d_out, int out_size) {
    const float* x = nullptr;
    const void* ei = nullptr;
    const float* w[4] = {nullptr, nullptr, nullptr, nullptr};
    const float* b[2] = {nullptr, nullptr};
    int nw = 0, nb = 0, E = 0, N = N_NODES;

    for (int i = 0; i < n_in; i++) {
        int sz = in_sizes[i];
        if (sz == N_NODES * NF) {
            x = (const float*)d_in[i];
        } else if (sz == NF * NF) {
            if (nw < 4) w[nw++] = (const float*)d_in[i];
        } else if (sz == NF) {
            if (nb < 2) b[nb++] = (const float*)d_in[i];
        } else {
            ei = d_in[i];
            E = sz / 2;
        }
    }
    if (E > E_MAX) E = E_MAX;
    const float *w1l = w[0], *w1r = w[1], *w2l = w[2], *w2r = w[3];
    const float *b1 = b[0], *b2 = b[1];
    float* out = (float*)d_out;

    size_t gemm_smem = (size_t)2 * 256 * 136 * sizeof(__nv_bfloat16)
                     + 128 * sizeof(float);   // ~136.5 KB
    cudaFuncSetAttribute(mma_gemm_kernel<true>,  cudaFuncAttributeMaxDynamicSharedMemorySize, (int)gemm_smem);
    cudaFuncSetAttribute(mma_gemm_kernel<false>, cudaFuncAttributeMaxDynamicSharedMemorySize, (int)gemm_smem);

    int agg_grid = (N_NODES * 32 + 511) / 512;

    init_kernel<<<(N_NODES + 511) / 512, 512>>>((const int*)ei);
    if (E > 0) hist_kernel<<<(E + 511) / 512, 512>>>(ei, E);
    scan1_kernel<<<SCAN_NBLK, SCAN_BLK>>>();
    scan23_kernel<<<SCAN_NBLK, SCAN_BLK>>>();
    if (E > 0) fill_kernel<<<(E + 511) / 512, 512>>>(ei, E);

    // Layer 1: [agg(x) | x] -> h (fp32, g_h4)
    aggregate_kernel<<<agg_grid, 512>>>(x, 0);
    mma_gemm_kernel<true><<<148, 384, gemm_smem>>>(x, w1l, w1r, b1, out, N, 0);

    // Layer 2: [agg(h) | h] -> out
    aggregate_kernel<<<agg_grid, 512>>>(x, 1);
    mma_gemm_kernel<false><<<148, 384, gemm_smem>>>(x, w2l, w2r, b2, out, N, 1);
}